// round 2
// baseline (speedup 1.0000x reference)
#include <cuda_runtime.h>
#include <cuda_bf16.h>
#include <math.h>

// Problem constants
#define BATCH 8
#define NTOK  4096
#define CDIM  768
#define HSP   64   // spatial h
#define WSP   64   // spatial w

// Scratch (device globals -- no runtime allocation allowed)
__device__ float g_M[CDIM * CDIM];                       // fused weight  [c][d]
__device__ float g_Z[(size_t)BATCH * NTOK * CDIM];       // x @ M
__device__ float g_Uc[(size_t)BATCH * NTOK * CDIM];      // cos-transform along s
__device__ float g_Us[(size_t)BATCH * NTOK * CDIM];      // sin-transform along s
__device__ float g_cos[64], g_sin[64];

// ---------------------------------------------------------------------------
// 0) twiddle tables: cos/sin(2*pi*i/64)
// ---------------------------------------------------------------------------
__global__ void init_tables_kernel() {
    int i = threadIdx.x;
    if (i < 64) {
        double ang = 6.283185307179586476925286766559 * (double)i / 64.0;
        g_cos[i] = (float)cos(ang);
        g_sin[i] = (float)sin(ang);
    }
}

// ---------------------------------------------------------------------------
// 1) M[c][d] = sum_j qkv_w[2C + j, c] * proj_w[d, j]      (768x768x768)
// ---------------------------------------------------------------------------
__global__ __launch_bounds__(256) void compute_M_kernel(
    const float* __restrict__ qkv_w, const float* __restrict__ proj_w)
{
    __shared__ float sA[16][17];  // [jj][cc]  from qkv_w (v block, transposed)
    __shared__ float sB[16][17];  // [jj][dd]  from proj_w (transposed)
    int tx = threadIdx.x;         // 0..15
    int ty = threadIdx.y;         // 0..15
    int c0 = blockIdx.y * 16;
    int d0 = blockIdx.x * 16;
    float acc = 0.f;
    for (int j0 = 0; j0 < CDIM; j0 += 16) {
        // coalesced: consecutive tx -> consecutive addresses
        sA[ty][tx] = qkv_w[(size_t)(2 * CDIM + j0 + ty) * CDIM + c0 + tx];
        sB[tx][ty] = proj_w[(size_t)(d0 + ty) * CDIM + j0 + tx];
        __syncthreads();
#pragma unroll
        for (int jj = 0; jj < 16; jj++)
            acc += sA[jj][ty] * sB[jj][tx];
        __syncthreads();
    }
    g_M[(size_t)(c0 + ty) * CDIM + d0 + tx] = acc;
}

// ---------------------------------------------------------------------------
// 2) Z = x @ M     [32768, 768] x [768, 768], classic 128x128 SIMT sgemm
// ---------------------------------------------------------------------------
__global__ __launch_bounds__(256) void sgemm_z_kernel(const float* __restrict__ A)
{
    const int K = CDIM, N = CDIM;
    __shared__ float As[16][128];   // transposed A tile
    __shared__ float Bs[16][128];
    int tid = threadIdx.x;
    int bm = blockIdx.y * 128;
    int bn = blockIdx.x * 128;

    int arow = tid >> 2;             // 0..63
    int acol = (tid & 3) << 2;       // 0,4,8,12
    int brow = tid >> 5;             // 0..7
    int bcol = (tid & 31) << 2;      // 0..124
    int ty = (tid >> 4) << 3;        // row offset 0..120
    int tx = (tid & 15) << 3;        // col offset 0..120

    float acc[8][8];
#pragma unroll
    for (int i = 0; i < 8; i++)
#pragma unroll
        for (int j = 0; j < 8; j++) acc[i][j] = 0.f;

    for (int k0 = 0; k0 < K; k0 += 16) {
        float4 a0 = *(const float4*)(A + (size_t)(bm + arow) * K + k0 + acol);
        float4 a1 = *(const float4*)(A + (size_t)(bm + arow + 64) * K + k0 + acol);
        float4 b0 = *(const float4*)(g_M + (size_t)(k0 + brow) * N + bn + bcol);
        float4 b1 = *(const float4*)(g_M + (size_t)(k0 + brow + 8) * N + bn + bcol);

        As[acol + 0][arow] = a0.x; As[acol + 1][arow] = a0.y;
        As[acol + 2][arow] = a0.z; As[acol + 3][arow] = a0.w;
        As[acol + 0][arow + 64] = a1.x; As[acol + 1][arow + 64] = a1.y;
        As[acol + 2][arow + 64] = a1.z; As[acol + 3][arow + 64] = a1.w;
        *(float4*)&Bs[brow][bcol]     = b0;
        *(float4*)&Bs[brow + 8][bcol] = b1;
        __syncthreads();

#pragma unroll
        for (int k = 0; k < 16; k++) {
            float a[8], b[8];
            *(float4*)&a[0] = *(const float4*)&As[k][ty];
            *(float4*)&a[4] = *(const float4*)&As[k][ty + 4];
            *(float4*)&b[0] = *(const float4*)&Bs[k][tx];
            *(float4*)&b[4] = *(const float4*)&Bs[k][tx + 4];
#pragma unroll
            for (int i = 0; i < 8; i++)
#pragma unroll
                for (int j = 0; j < 8; j++)
                    acc[i][j] += a[i] * b[j];
        }
        __syncthreads();
    }

#pragma unroll
    for (int i = 0; i < 8; i++) {
        float* crow = g_Z + (size_t)(bm + ty + i) * N + bn + tx;
        *(float4*)(crow + 0) = make_float4(acc[i][0], acc[i][1], acc[i][2], acc[i][3]);
        *(float4*)(crow + 4) = make_float4(acc[i][4], acc[i][5], acc[i][6], acc[i][7]);
    }
}

// ---------------------------------------------------------------------------
// 3) Pass 1: DFT along inner spatial dim s (w).
//    Uc[b,r,q,ch] = sum_s cos(2*pi*q*s/64) * Z[b, r*64+s, ch]
//    Us[b,r,q,ch] = sum_s sin(2*pi*q*s/64) * Z[b, r*64+s, ch]
//    grid: (C/128, 64 r, 8 b), 256 threads, 128-channel tile in smem
// ---------------------------------------------------------------------------
__global__ __launch_bounds__(256) void pass1_kernel(const float* __restrict__ /*unused*/)
{
    __shared__ float sZ[64][128];
    __shared__ float sc[64], ss[64];
    int b = blockIdx.z, r = blockIdx.y, c0 = blockIdx.x * 128;
    int tid = threadIdx.x;
    if (tid < 64) { sc[tid] = g_cos[tid]; ss[tid] = g_sin[tid]; }
    for (int i = tid; i < 64 * 128; i += 256) {
        int s = i >> 7, ch = i & 127;
        sZ[s][ch] = g_Z[((size_t)b * NTOK + r * 64 + s) * CDIM + c0 + ch];
    }
    __syncthreads();
    int ch = tid & 127;
    int qh = tid >> 7;           // 0 or 1
    for (int q = qh; q < 64; q += 2) {
        float ac = 0.f, as = 0.f;
#pragma unroll 16
        for (int s = 0; s < 64; s++) {
            int idx = (q * s) & 63;
            float z = sZ[s][ch];
            ac += sc[idx] * z;
            as += ss[idx] * z;
        }
        size_t o = (((size_t)b * 64 + r) * 64 + q) * CDIM + c0 + ch;
        g_Uc[o] = ac;
        g_Us[o] = as;
    }
}

// ---------------------------------------------------------------------------
// 4) Pass 2: DFT along outer spatial dim r (h), take real part, add bias.
//    out[b, p*64+q, ch] = sum_r cos(2*pi*p*r/64)*Uc[b,r,q,ch]
//                       - sin(2*pi*p*r/64)*Us[b,r,q,ch] + bias[ch]
//    grid: (C/64, 64 q, 8 b), 256 threads, 64-channel tile in smem
// ---------------------------------------------------------------------------
__global__ __launch_bounds__(256) void pass2_kernel(
    const float* __restrict__ bias, float* __restrict__ out)
{
    __shared__ float sUc[64][64];
    __shared__ float sUs[64][64];
    __shared__ float sc[64], ss[64];
    int b = blockIdx.z, q = blockIdx.y, c0 = blockIdx.x * 64;
    int tid = threadIdx.x;
    if (tid < 64) { sc[tid] = g_cos[tid]; ss[tid] = g_sin[tid]; }
    for (int i = tid; i < 64 * 64; i += 256) {
        int r = i >> 6, chl = i & 63;
        size_t o = (((size_t)b * 64 + r) * 64 + q) * CDIM + c0 + chl;
        sUc[r][chl] = g_Uc[o];
        sUs[r][chl] = g_Us[o];
    }
    __syncthreads();
    int ch = tid & 63;
    int ph = tid >> 6;          // 0..3
    float bv = bias[c0 + ch];
    for (int p = ph; p < 64; p += 4) {
        float acc = bv;
#pragma unroll 16
        for (int r = 0; r < 64; r++) {
            int idx = (p * r) & 63;
            acc += sc[idx] * sUc[r][ch] - ss[idx] * sUs[r][ch];
        }
        out[((size_t)b * NTOK + p * 64 + q) * CDIM + c0 + ch] = acc;
    }
}

// ---------------------------------------------------------------------------
// launch
// ---------------------------------------------------------------------------
extern "C" void kernel_launch(void* const* d_in, const int* in_sizes, int n_in,
                              void* d_out, int out_size)
{
    const float* x      = (const float*)d_in[0];   // [8,4096,768]
    const float* qkv_w  = (const float*)d_in[1];   // [2304,768]
    const float* proj_w = (const float*)d_in[2];   // [768,768]
    const float* proj_b = (const float*)d_in[3];   // [768]
    float* out = (float*)d_out;

    init_tables_kernel<<<1, 64>>>();
    compute_M_kernel<<<dim3(CDIM / 16, CDIM / 16), dim3(16, 16)>>>(qkv_w, proj_w);
    sgemm_z_kernel<<<dim3(CDIM / 128, (BATCH * NTOK) / 128), 256>>>(x);
    pass1_kernel<<<dim3(CDIM / 128, 64, BATCH), 256>>>(x);
    pass2_kernel<<<dim3(CDIM / 64, 64, BATCH), 256>>>(proj_b, out);
}

// round 4
// speedup vs baseline: 2.1736x; 2.1736x over previous
#include <cuda_runtime.h>
#include <cuda_bf16.h>
#include <cstdint>
#include <math.h>

// Problem constants
#define BATCH 8
#define NTOK  4096
#define CDIM  768

// ---------------------------------------------------------------------------
// device scratch (no runtime allocation allowed)
// ---------------------------------------------------------------------------
__device__ float g_M[CDIM * CDIM];                                  // fused weight [c][d]
__device__ float g_Z[(size_t)BATCH * NTOK * CDIM];                  // x @ M
__device__ float g_Uc[(size_t)BATCH * NTOK * CDIM];
__device__ float g_Us[(size_t)BATCH * NTOK * CDIM];
__device__ float g_T1t[64][128];                                    // [s][i] i<64: cos(q=i), i>=64: sin
__device__ float g_T2t[128][64];                                    // [k][p] k<64: cos(p*k), k>=64: -sin
__device__ __align__(16) __nv_bfloat16 g_Abf[(size_t)BATCH * NTOK * 2 * CDIM]; // [32768][1536]: [xh | xl]
__device__ __align__(16) __nv_bfloat16 g_Bbf[(size_t)2 * CDIM * CDIM];         // [768 n][1536 k]: [Mh | Ml]

// ---------------------------------------------------------------------------
// PTX helpers (baseline compute_103-safe: cp.async / ldmatrix / mma.sync only)
// ---------------------------------------------------------------------------
__device__ __forceinline__ uint32_t smem_u32(const void* p) {
    uint32_t a;
    asm("{ .reg .u64 t; cvta.to.shared.u64 t, %1; cvt.u32.u64 %0, t; }" : "=r"(a) : "l"(p));
    return a;
}
__device__ __forceinline__ void cp_async16(uint32_t sa, const void* ga) {
    asm volatile("cp.async.cg.shared.global [%0], [%1], 16;" :: "r"(sa), "l"(ga));
}
#define CP_COMMIT() asm volatile("cp.async.commit_group;" ::: "memory")
#define CP_WAIT1()  asm volatile("cp.async.wait_group 1;" ::: "memory")
#define CP_WAIT0()  asm volatile("cp.async.wait_group 0;" ::: "memory")
#define SWZ128(o)   ((o) ^ (((o) >> 3) & 0x70))

__device__ __forceinline__ void ldmx4(uint32_t* r, uint32_t addr) {
    asm volatile("ldmatrix.sync.aligned.m8n8.x4.shared.b16 {%0,%1,%2,%3}, [%4];"
                 : "=r"(r[0]), "=r"(r[1]), "=r"(r[2]), "=r"(r[3]) : "r"(addr));
}
__device__ __forceinline__ void mma16816(float* d, const uint32_t* a, uint32_t b0, uint32_t b1) {
    asm volatile("mma.sync.aligned.m16n8k16.row.col.f32.bf16.bf16.f32 "
                 "{%0,%1,%2,%3},{%4,%5,%6,%7},{%8,%9},{%0,%1,%2,%3};"
                 : "+f"(d[0]), "+f"(d[1]), "+f"(d[2]), "+f"(d[3])
                 : "r"(a[0]), "r"(a[1]), "r"(a[2]), "r"(a[3]), "r"(b0), "r"(b1));
}

// ---------------------------------------------------------------------------
// 0) twiddle matrices
// ---------------------------------------------------------------------------
__global__ void init_tables_kernel() {
    int tid = threadIdx.x;
    const double TWO_PI = 6.283185307179586476925286766559;
    for (int i = tid; i < 64 * 128; i += 256) {
        int s = i >> 7, col = i & 127;
        int q = col & 63;
        double ang = TWO_PI * (double)((q * s) & 63) / 64.0;
        g_T1t[s][col] = (col < 64) ? (float)cos(ang) : (float)sin(ang);
    }
    for (int i = tid; i < 128 * 64; i += 256) {
        int k = i >> 6, p = i & 63;
        int r = k & 63;
        double ang = TWO_PI * (double)((p * r) & 63) / 64.0;
        g_T2t[k][p] = (k < 64) ? (float)cos(ang) : (float)(-sin(ang));
    }
}

// ---------------------------------------------------------------------------
// 1) M[c][d] = sum_j qkv_w[2C + j, c] * proj_w[d, j]
// ---------------------------------------------------------------------------
__global__ __launch_bounds__(256) void compute_M_kernel(
    const float* __restrict__ qkv_w, const float* __restrict__ proj_w)
{
    __shared__ float sA[16][17];
    __shared__ float sB[16][17];
    int tx = threadIdx.x, ty = threadIdx.y;
    int c0 = blockIdx.y * 16, d0 = blockIdx.x * 16;
    float acc = 0.f;
    for (int j0 = 0; j0 < CDIM; j0 += 16) {
        sA[ty][tx] = qkv_w[(size_t)(2 * CDIM + j0 + ty) * CDIM + c0 + tx];
        sB[tx][ty] = proj_w[(size_t)(d0 + ty) * CDIM + j0 + tx];
        __syncthreads();
#pragma unroll
        for (int jj = 0; jj < 16; jj++)
            acc += sA[jj][ty] * sB[jj][tx];
        __syncthreads();
    }
    g_M[(size_t)(c0 + ty) * CDIM + d0 + tx] = acc;
}

// ---------------------------------------------------------------------------
// 2a) split x into bf16 hi/lo:  g_Abf[row][0:768)=xh, [768:1536)=xl
// ---------------------------------------------------------------------------
__global__ __launch_bounds__(256) void prep_a_kernel(const float* __restrict__ x) {
    size_t i = (size_t)blockIdx.x * 256 + threadIdx.x;
    if (i >= (size_t)BATCH * NTOK * CDIM) return;
    size_t row = i / CDIM;
    int c = (int)(i % CDIM);
    float v = x[i];
    __nv_bfloat16 h = __float2bfloat16(v);
    __nv_bfloat16 l = __float2bfloat16(v - __bfloat162float(h));
    g_Abf[row * 1536 + c] = h;
    g_Abf[row * 1536 + 768 + c] = l;
}

// ---------------------------------------------------------------------------
// 2b) B operand: Bbf[n][k] : k<768 -> hi(M[k][n]) ; k>=768 -> lo(M[k-768][n])
// ---------------------------------------------------------------------------
__global__ __launch_bounds__(256) void prep_b_kernel() {
    size_t i = (size_t)blockIdx.x * 256 + threadIdx.x;
    if (i >= (size_t)CDIM * 2 * CDIM) return;
    int n = (int)(i / 1536);
    int k = (int)(i % 1536);
    float v = g_M[(size_t)(k % 768) * CDIM + n];
    __nv_bfloat16 h = __float2bfloat16(v);
    g_Bbf[i] = (k < 768) ? h : __float2bfloat16(v - __bfloat162float(h));
}

// ---------------------------------------------------------------------------
// 3) Z = x @ M via mma.sync bf16 split-precision GEMM
//    logical K = 3*768 over stored K=1536:
//      seg0: xh*Mh   seg1: xh*Ml   seg2: xl*Mh
//    CTA 128(M) x 128(N), K-tile 64 bf16 (128B rows, SW128), 2-stage cp.async
//    8 warps, warp tile 32(M) x 64(N), m16n8k16 HMMA
// ---------------------------------------------------------------------------
#define GM_NT 36
#define STG_BYTES 32768          /* A 16KB + B 16KB per stage */

__device__ __forceinline__ void gemm_load_tile(uint32_t sb, int tid, int bm, int bn,
                                               int kt, int buf) {
    int seg = kt / 12;
    int kl = (kt % 12) * 64;
    int aoff = ((seg == 2) ? 768 : 0) + kl;   // bf16 elements
    int boff = ((seg == 1) ? 768 : 0) + kl;
    uint32_t abase = sb + buf * STG_BYTES;
    uint32_t bbase = abase + 16384;
#pragma unroll
    for (int c = 0; c < 4; c++) {
        int ch = tid + c * 256;               // 0..1023: 128 rows x 8 chunks
        int row = ch >> 3, kc = ch & 7;
        cp_async16(abase + SWZ128(row * 128 + kc * 16),
                   g_Abf + (size_t)(bm + row) * 1536 + aoff + kc * 8);
    }
#pragma unroll
    for (int c = 0; c < 4; c++) {
        int ch = tid + c * 256;
        int row = ch >> 3, kc = ch & 7;
        cp_async16(bbase + SWZ128(row * 128 + kc * 16),
                   g_Bbf + (size_t)(bn + row) * 1536 + boff + kc * 8);
    }
}

__global__ __launch_bounds__(256) void gemm_mma_kernel() {
    extern __shared__ char smem[];
    uint32_t sb = smem_u32(smem);
    int tid = threadIdx.x;
    int wid = tid >> 5, lane = tid & 31;
    int wm = wid >> 1, wn = wid & 1;          // warp grid 4(m) x 2(n)
    int bm = blockIdx.y * 128;
    int bn = blockIdx.x * 128;

    int l7 = lane & 7, sel = lane >> 3;       // ldmatrix source-row selectors
    int rsel = (sel & 1) * 8;
    int csel = (sel >> 1) * 16;

    float acc[2][8][4];
#pragma unroll
    for (int i = 0; i < 2; i++)
#pragma unroll
        for (int j = 0; j < 8; j++)
#pragma unroll
            for (int v = 0; v < 4; v++) acc[i][j][v] = 0.f;

    gemm_load_tile(sb, tid, bm, bn, 0, 0);
    CP_COMMIT();

    for (int kt = 0; kt < GM_NT; kt++) {
        if (kt + 1 < GM_NT) {
            gemm_load_tile(sb, tid, bm, bn, kt + 1, (kt + 1) & 1);
            CP_COMMIT();
            CP_WAIT1();
        } else {
            CP_WAIT0();
        }
        __syncthreads();

        uint32_t ab = sb + (kt & 1) * STG_BYTES;
        uint32_t bb = ab + 16384;
#pragma unroll
        for (int ks = 0; ks < 4; ks++) {
            uint32_t afrag[2][4];
#pragma unroll
            for (int mt = 0; mt < 2; mt++) {
                int row = wm * 32 + mt * 16 + l7 + rsel;
                ldmx4(afrag[mt], ab + SWZ128(row * 128 + ks * 32 + csel));
            }
#pragma unroll
            for (int nt = 0; nt < 4; nt++) {
                uint32_t bfrag[4];
                int row = wn * 64 + nt * 16 + l7 + rsel;
                ldmx4(bfrag, bb + SWZ128(row * 128 + ks * 32 + csel));
#pragma unroll
                for (int mt = 0; mt < 2; mt++) {
                    mma16816(acc[mt][nt * 2 + 0], afrag[mt], bfrag[0], bfrag[2]);
                    mma16816(acc[mt][nt * 2 + 1], afrag[mt], bfrag[1], bfrag[3]);
                }
            }
        }
        __syncthreads();
    }

    // epilogue: C fragment m16n8 -> g_Z
    int rq = lane >> 2, cq = (lane & 3) * 2;
#pragma unroll
    for (int mt = 0; mt < 2; mt++) {
#pragma unroll
        for (int n8 = 0; n8 < 8; n8++) {
            float* d = acc[mt][n8];
            size_t r0 = (size_t)bm + wm * 32 + mt * 16 + rq;
            int c = bn + wn * 64 + n8 * 8 + cq;
            *(float2*)(g_Z + r0 * CDIM + c)       = make_float2(d[0], d[1]);
            *(float2*)(g_Z + (r0 + 8) * CDIM + c) = make_float2(d[2], d[3]);
        }
    }
}

// ---------------------------------------------------------------------------
// 4) Pass 1 as register-tiled GEMM: per (b, r):
//    [Uc;Us][i][ch] = sum_s T1t[s][i] * Z[b, r*64+s, ch]
//    block: 128(M=cos64+sin64) x 128(ch), K=64, 8x8 microkernel, 256 thr
// ---------------------------------------------------------------------------
__global__ __launch_bounds__(256) void pass1_kernel() {
    extern __shared__ float sm1[];
    float (*sT)[128] = (float(*)[128])sm1;              // [64][128] = T1t
    float (*sZ)[128] = (float(*)[128])(sm1 + 64 * 128); // [64][128]
    int b = blockIdx.z, r = blockIdx.y, c0 = blockIdx.x * 128;
    int tid = threadIdx.x;
    for (int i = tid; i < 64 * 128; i += 256) {
        int row = i >> 7, col = i & 127;
        sT[row][col] = g_T1t[row][col];
        sZ[row][col] = g_Z[((size_t)b * NTOK + r * 64 + row) * CDIM + c0 + col];
    }
    __syncthreads();

    int ty = (tid >> 4) << 3;
    int tx = (tid & 15) << 3;
    float acc[8][8];
#pragma unroll
    for (int i = 0; i < 8; i++)
#pragma unroll
        for (int j = 0; j < 8; j++) acc[i][j] = 0.f;

#pragma unroll 8
    for (int k = 0; k < 64; k++) {
        float a[8], bb[8];
        *(float4*)&a[0] = *(const float4*)&sT[k][ty];
        *(float4*)&a[4] = *(const float4*)&sT[k][ty + 4];
        *(float4*)&bb[0] = *(const float4*)&sZ[k][tx];
        *(float4*)&bb[4] = *(const float4*)&sZ[k][tx + 4];
#pragma unroll
        for (int i = 0; i < 8; i++)
#pragma unroll
            for (int j = 0; j < 8; j++)
                acc[i][j] += a[i] * bb[j];
    }

#pragma unroll
    for (int i = 0; i < 8; i++) {
        int row = ty + i;
        int q = row & 63;
        float* base = (row < 64) ? g_Uc : g_Us;
        float* dst = base + (((size_t)b * 64 + r) * 64 + q) * CDIM + c0 + tx;
        *(float4*)(dst + 0) = make_float4(acc[i][0], acc[i][1], acc[i][2], acc[i][3]);
        *(float4*)(dst + 4) = make_float4(acc[i][4], acc[i][5], acc[i][6], acc[i][7]);
    }
}

// ---------------------------------------------------------------------------
// 5) Pass 2 as register-tiled GEMM: per (b, q):
//    out[p][ch] = sum_k T2t[k][p] * V[k][ch] + bias,  V = [Uc(r=k) ; Us(r=k-64)]
//    block: 64(p) x 128(ch), K=128, 8x4 microkernel, 256 thr
// ---------------------------------------------------------------------------
__global__ __launch_bounds__(256) void pass2_kernel(
    const float* __restrict__ bias, float* __restrict__ out)
{
    extern __shared__ float sm2[];
    float (*sT2)[64] = (float(*)[64])sm2;                  // [128][64]
    float (*sV)[128] = (float(*)[128])(sm2 + 128 * 64);    // [128][128]
    int b = blockIdx.z, q = blockIdx.y, c0 = blockIdx.x * 128;
    int tid = threadIdx.x;

    for (int i = tid; i < 128 * 64; i += 256) {
        int k = i >> 6, p = i & 63;
        sT2[k][p] = g_T2t[k][p];
    }
    for (int i = tid; i < 128 * 128; i += 256) {
        int k = i >> 7, col = i & 127;
        const float* src = (k < 64)
            ? g_Uc + (((size_t)b * 64 + k) * 64 + q) * CDIM + c0 + col
            : g_Us + (((size_t)b * 64 + (k - 64)) * 64 + q) * CDIM + c0 + col;
        sV[k][col] = *src;
    }
    __syncthreads();

    int ty = (tid >> 5) << 3;   // p base
    int tx = (tid & 31) << 2;   // ch base
    float acc[8][4];
#pragma unroll
    for (int i = 0; i < 8; i++)
#pragma unroll
        for (int j = 0; j < 4; j++) acc[i][j] = 0.f;

#pragma unroll 8
    for (int k = 0; k < 128; k++) {
        float a[8];
        *(float4*)&a[0] = *(const float4*)&sT2[k][ty];
        *(float4*)&a[4] = *(const float4*)&sT2[k][ty + 4];
        float4 bv = *(const float4*)&sV[k][tx];
#pragma unroll
        for (int i = 0; i < 8; i++) {
            acc[i][0] += a[i] * bv.x;
            acc[i][1] += a[i] * bv.y;
            acc[i][2] += a[i] * bv.z;
            acc[i][3] += a[i] * bv.w;
        }
    }

    float4 bias4 = *(const float4*)(bias + c0 + tx);
#pragma unroll
    for (int i = 0; i < 8; i++) {
        int p = ty + i;
        float4 f = make_float4(acc[i][0] + bias4.x, acc[i][1] + bias4.y,
                               acc[i][2] + bias4.z, acc[i][3] + bias4.w);
        *(float4*)(out + ((size_t)b * NTOK + p * 64 + q) * CDIM + c0 + tx) = f;
    }
}

// ---------------------------------------------------------------------------
// launch
// ---------------------------------------------------------------------------
extern "C" void kernel_launch(void* const* d_in, const int* in_sizes, int n_in,
                              void* d_out, int out_size)
{
    const float* x      = (const float*)d_in[0];   // [8,4096,768]
    const float* qkv_w  = (const float*)d_in[1];   // [2304,768]
    const float* proj_w = (const float*)d_in[2];   // [768,768]
    const float* proj_b = (const float*)d_in[3];   // [768]
    float* out = (float*)d_out;

    cudaFuncSetAttribute(gemm_mma_kernel, cudaFuncAttributeMaxDynamicSharedMemorySize, 2 * STG_BYTES);
    cudaFuncSetAttribute(pass1_kernel,    cudaFuncAttributeMaxDynamicSharedMemorySize, 65536);
    cudaFuncSetAttribute(pass2_kernel,    cudaFuncAttributeMaxDynamicSharedMemorySize, 98304);

    init_tables_kernel<<<1, 256>>>();
    compute_M_kernel<<<dim3(CDIM / 16, CDIM / 16), dim3(16, 16)>>>(qkv_w, proj_w);
    prep_b_kernel<<<(int)(((size_t)CDIM * 2 * CDIM + 255) / 256), 256>>>();
    prep_a_kernel<<<(int)(((size_t)BATCH * NTOK * CDIM + 255) / 256), 256>>>(x);
    gemm_mma_kernel<<<dim3(CDIM / 128, (BATCH * NTOK) / 128), 256, 2 * STG_BYTES>>>();
    pass1_kernel<<<dim3(CDIM / 128, 64, BATCH), 256, 65536>>>();
    pass2_kernel<<<dim3(CDIM / 128, 64, BATCH), 256, 98304>>>(proj_b, out);
}

// round 5
// speedup vs baseline: 2.8625x; 1.3170x over previous
#include <cuda_runtime.h>
#include <cuda_bf16.h>
#include <cstdint>
#include <math.h>

// Problem constants
#define BATCH 8
#define NTOK  4096
#define CDIM  768

// ---------------------------------------------------------------------------
// device scratch (no runtime allocation allowed)
// ---------------------------------------------------------------------------
__device__ float g_M[CDIM * CDIM];                                   // fused weight [c][d]
__device__ __align__(16) __nv_bfloat16 g_Abf[(size_t)BATCH * NTOK * 2 * CDIM]; // [32768][1536]: [xh|xl]
__device__ __align__(16) __nv_bfloat16 g_Bbf[(size_t)2 * CDIM * CDIM];         // [768 n][1536]: [Mh|Ml]
__device__ __align__(16) __nv_bfloat16 g_Zbf[(size_t)BATCH * NTOK * 2 * CDIM]; // [32768][1536]: [Zh|Zl]
__device__ __align__(16) __nv_bfloat16 g_Ubf[(size_t)BATCH * 64 * 128 * 2 * CDIM]; // [(b,q,k)][1536]: [Uh|Ul]
__device__ __align__(16) __nv_bfloat16 g_T1bf[2 * 128 * 64];         // [chunk][i][s]  chunk0=hi, 1=lo
__device__ __align__(16) __nv_bfloat16 g_T2bf[4 * 64 * 64];          // [chunk][p][kk] 0,1=hi(k0..63,64..127) 2,3=lo

// ---------------------------------------------------------------------------
// PTX helpers (baseline compute_103-safe)
// ---------------------------------------------------------------------------
__device__ __forceinline__ uint32_t smem_u32(const void* p) {
    uint32_t a;
    asm("{ .reg .u64 t; cvta.to.shared.u64 t, %1; cvt.u32.u64 %0, t; }" : "=r"(a) : "l"(p));
    return a;
}
__device__ __forceinline__ void cp_async16(uint32_t sa, const void* ga) {
    asm volatile("cp.async.cg.shared.global [%0], [%1], 16;" :: "r"(sa), "l"(ga));
}
#define CP_COMMIT() asm volatile("cp.async.commit_group;" ::: "memory")
#define CP_WAIT1()  asm volatile("cp.async.wait_group 1;" ::: "memory")
#define CP_WAIT0()  asm volatile("cp.async.wait_group 0;" ::: "memory")
#define SWZ128(o)   ((o) ^ (((o) >> 3) & 0x70))

__device__ __forceinline__ void ldmx4(uint32_t* r, uint32_t addr) {
    asm volatile("ldmatrix.sync.aligned.m8n8.x4.shared.b16 {%0,%1,%2,%3}, [%4];"
                 : "=r"(r[0]), "=r"(r[1]), "=r"(r[2]), "=r"(r[3]) : "r"(addr));
}
__device__ __forceinline__ void ldmx4t(uint32_t* r, uint32_t addr) {
    asm volatile("ldmatrix.sync.aligned.m8n8.x4.trans.shared.b16 {%0,%1,%2,%3}, [%4];"
                 : "=r"(r[0]), "=r"(r[1]), "=r"(r[2]), "=r"(r[3]) : "r"(addr));
}
__device__ __forceinline__ void mma16816(float* d, const uint32_t* a, uint32_t b0, uint32_t b1) {
    asm volatile("mma.sync.aligned.m16n8k16.row.col.f32.bf16.bf16.f32 "
                 "{%0,%1,%2,%3},{%4,%5,%6,%7},{%8,%9},{%0,%1,%2,%3};"
                 : "+f"(d[0]), "+f"(d[1]), "+f"(d[2]), "+f"(d[3])
                 : "r"(a[0]), "r"(a[1]), "r"(a[2]), "r"(a[3]), "r"(b0), "r"(b1));
}
// write (a,b) as bf16x2 hi at p, bf16x2 lo at p+768
__device__ __forceinline__ void store_split(__nv_bfloat16* p, float a, float b) {
    __nv_bfloat16 ha = __float2bfloat16(a), hb = __float2bfloat16(b);
    __nv_bfloat162 h; h.x = ha; h.y = hb;
    *(__nv_bfloat162*)p = h;
    __nv_bfloat162 l;
    l.x = __float2bfloat16(a - __bfloat162float(ha));
    l.y = __float2bfloat16(b - __bfloat162float(hb));
    *(__nv_bfloat162*)(p + 768) = l;
}

// ---------------------------------------------------------------------------
// 0) twiddle tables (bf16 hi/lo split)
// ---------------------------------------------------------------------------
__global__ void init_tables_kernel() {
    int tid = threadIdx.x;
    const double TWO_PI = 6.283185307179586476925286766559;
    for (int i = tid; i < 128 * 64; i += 256) {
        int row = i >> 6, s = i & 63;
        double ang = TWO_PI * (double)(((row & 63) * s) & 63) / 64.0;
        float v = (row < 64) ? (float)cos(ang) : (float)sin(ang);
        __nv_bfloat16 h = __float2bfloat16(v);
        g_T1bf[i] = h;
        g_T1bf[128 * 64 + i] = __float2bfloat16(v - __bfloat162float(h));
    }
    for (int i = tid; i < 64 * 128; i += 256) {
        int p = i >> 7, k = i & 127;
        double ang = TWO_PI * (double)((p * (k & 63)) & 63) / 64.0;
        float v = (k < 64) ? (float)cos(ang) : (float)(-sin(ang));
        __nv_bfloat16 h = __float2bfloat16(v);
        int chunk = k >> 6, kk = k & 63;
        g_T2bf[chunk * 4096 + p * 64 + kk] = h;
        g_T2bf[(2 + chunk) * 4096 + p * 64 + kk] = __float2bfloat16(v - __bfloat162float(h));
    }
}

// ---------------------------------------------------------------------------
// 1) M[c][d] = sum_j qkv_w[2C + j, c] * proj_w[d, j]
// ---------------------------------------------------------------------------
__global__ __launch_bounds__(256) void compute_M_kernel(
    const float* __restrict__ qkv_w, const float* __restrict__ proj_w)
{
    __shared__ float sA[16][17];
    __shared__ float sB[16][17];
    int tx = threadIdx.x, ty = threadIdx.y;
    int c0 = blockIdx.y * 16, d0 = blockIdx.x * 16;
    float acc = 0.f;
    for (int j0 = 0; j0 < CDIM; j0 += 16) {
        sA[ty][tx] = qkv_w[(size_t)(2 * CDIM + j0 + ty) * CDIM + c0 + tx];
        sB[tx][ty] = proj_w[(size_t)(d0 + ty) * CDIM + j0 + tx];
        __syncthreads();
#pragma unroll
        for (int jj = 0; jj < 16; jj++)
            acc += sA[jj][ty] * sB[jj][tx];
        __syncthreads();
    }
    g_M[(size_t)(c0 + ty) * CDIM + d0 + tx] = acc;
}

// ---------------------------------------------------------------------------
// 2a) split x -> bf16 hi/lo, vectorized x4
// ---------------------------------------------------------------------------
__global__ __launch_bounds__(256) void prep_a_kernel(const float* __restrict__ x) {
    size_t idx = (size_t)blockIdx.x * 256 + threadIdx.x;
    size_t i4 = idx * 4;
    if (i4 >= (size_t)BATCH * NTOK * CDIM) return;
    size_t row = i4 / CDIM;
    int c = (int)(i4 % CDIM);
    float4 v = *(const float4*)(x + i4);
    __nv_bfloat16* dst = g_Abf + row * 1536 + c;
    store_split(dst + 0, v.x, v.y);        // writes hi at dst, lo at dst+768
    store_split(dst + 2, v.z, v.w);
}

// ---------------------------------------------------------------------------
// 2b) B operand: tiled transpose of g_M with hi/lo split
//     g_Bbf[n][k] = hi(M[k][n]); g_Bbf[n][768+k] = lo
// ---------------------------------------------------------------------------
__global__ __launch_bounds__(256) void prep_b_kernel() {
    __shared__ float tile[32][33];
    int k0 = blockIdx.x * 32, n0 = blockIdx.y * 32;
    int tx = threadIdx.x & 31, ty = threadIdx.x >> 5;   // 32 x 8
#pragma unroll
    for (int j = 0; j < 4; j++)
        tile[ty + j * 8][tx] = g_M[(size_t)(k0 + ty + j * 8) * CDIM + n0 + tx];
    __syncthreads();
#pragma unroll
    for (int j = 0; j < 4; j++) {
        int n = n0 + ty + j * 8;
        int k = k0 + tx;
        float v = tile[tx][ty + j * 8];
        __nv_bfloat16 h = __float2bfloat16(v);
        g_Bbf[(size_t)n * 1536 + k] = h;
        g_Bbf[(size_t)n * 1536 + 768 + k] = __float2bfloat16(v - __bfloat162float(h));
    }
}

// ---------------------------------------------------------------------------
// 3) Z = x @ M via mma.sync bf16 split GEMM; epilogue writes Z in split bf16
//    CTA 128x128, K-tile 64, 2-stage cp.async, 8 warps (4m x 2n)
// ---------------------------------------------------------------------------
#define GM_NT 36
#define STG_BYTES 32768

__device__ __forceinline__ void gemm_load_tile(uint32_t sb, int tid, int bm, int bn,
                                               int kt, int buf) {
    int seg = kt / 12;
    int kl = (kt % 12) * 64;
    int aoff = ((seg == 2) ? 768 : 0) + kl;
    int boff = ((seg == 1) ? 768 : 0) + kl;
    uint32_t abase = sb + buf * STG_BYTES;
    uint32_t bbase = abase + 16384;
#pragma unroll
    for (int c = 0; c < 4; c++) {
        int ch = tid + c * 256;
        int row = ch >> 3, kc = ch & 7;
        cp_async16(abase + SWZ128(row * 128 + kc * 16),
                   g_Abf + (size_t)(bm + row) * 1536 + aoff + kc * 8);
    }
#pragma unroll
    for (int c = 0; c < 4; c++) {
        int ch = tid + c * 256;
        int row = ch >> 3, kc = ch & 7;
        cp_async16(bbase + SWZ128(row * 128 + kc * 16),
                   g_Bbf + (size_t)(bn + row) * 1536 + boff + kc * 8);
    }
}

__global__ __launch_bounds__(256) void gemm_mma_kernel() {
    extern __shared__ char smem[];
    uint32_t sb = smem_u32(smem);
    int tid = threadIdx.x;
    int wid = tid >> 5, lane = tid & 31;
    int wm = wid >> 1, wn = wid & 1;
    int bm = blockIdx.y * 128;
    int bn = blockIdx.x * 128;

    int l7 = lane & 7, sel = lane >> 3;
    int rsel = (sel & 1) * 8;
    int csel = (sel >> 1) * 16;

    float acc[2][8][4];
#pragma unroll
    for (int i = 0; i < 2; i++)
#pragma unroll
        for (int j = 0; j < 8; j++)
#pragma unroll
            for (int v = 0; v < 4; v++) acc[i][j][v] = 0.f;

    gemm_load_tile(sb, tid, bm, bn, 0, 0);
    CP_COMMIT();

    for (int kt = 0; kt < GM_NT; kt++) {
        if (kt + 1 < GM_NT) {
            gemm_load_tile(sb, tid, bm, bn, kt + 1, (kt + 1) & 1);
            CP_COMMIT();
            CP_WAIT1();
        } else {
            CP_WAIT0();
        }
        __syncthreads();

        uint32_t ab = sb + (kt & 1) * STG_BYTES;
        uint32_t bb = ab + 16384;
#pragma unroll
        for (int ks = 0; ks < 4; ks++) {
            uint32_t afrag[2][4];
#pragma unroll
            for (int mt = 0; mt < 2; mt++) {
                int row = wm * 32 + mt * 16 + l7 + rsel;
                ldmx4(afrag[mt], ab + SWZ128(row * 128 + ks * 32 + csel));
            }
#pragma unroll
            for (int nt = 0; nt < 4; nt++) {
                uint32_t bfrag[4];
                int row = wn * 64 + nt * 16 + l7 + rsel;
                ldmx4(bfrag, bb + SWZ128(row * 128 + ks * 32 + csel));
#pragma unroll
                for (int mt = 0; mt < 2; mt++) {
                    mma16816(acc[mt][nt * 2 + 0], afrag[mt], bfrag[0], bfrag[2]);
                    mma16816(acc[mt][nt * 2 + 1], afrag[mt], bfrag[1], bfrag[3]);
                }
            }
        }
        __syncthreads();
    }

    int rq = lane >> 2, cq = (lane & 3) * 2;
#pragma unroll
    for (int mt = 0; mt < 2; mt++) {
#pragma unroll
        for (int n8 = 0; n8 < 8; n8++) {
            float* d = acc[mt][n8];
            size_t r0 = (size_t)bm + wm * 32 + mt * 16 + rq;
            int c = bn + wn * 64 + n8 * 8 + cq;
            store_split(g_Zbf + r0 * 1536 + c, d[0], d[1]);
            store_split(g_Zbf + (r0 + 8) * 1536 + c, d[2], d[3]);
        }
    }
}

// ---------------------------------------------------------------------------
// 4) Pass 1 (mma): per (b, r, chtile): U[128i x 128ch] = T1 * Z, 3-term split
//    K logical 192: ks 0..3 Th*Zh, 4..7 Th*Zl, 8..11 Tl*Zh
//    smem: A [2 chunk][128][64], B [2 nh][128 krow][64]  (krow<64: Zh, >=64: Zl)
// ---------------------------------------------------------------------------
__global__ __launch_bounds__(256) void pass1_kernel() {
    extern __shared__ char smem[];
    uint32_t sb = smem_u32(smem);
    uint32_t sbA = sb, sbB = sb + 32768;
    int b = blockIdx.z, r = blockIdx.y, c0 = blockIdx.x * 128;
    int tid = threadIdx.x;
    int wid = tid >> 5, lane = tid & 31;
    int wm = wid >> 1, wn = wid & 1;

    // load A (32KB linear)
#pragma unroll
    for (int c = 0; c < 8; c++) {
        int o = (tid + c * 256) * 16;
        cp_async16(sbA + SWZ128(o), (const char*)g_T1bf + o);
    }
    // load B
#pragma unroll
    for (int c = 0; c < 8; c++) {
        int idx = tid + c * 256;                // 0..2047
        int nh = idx >> 10;
        int rem = idx & 1023;
        int krow = rem >> 3, kc = rem & 7;
        int s = krow & 63, part = krow >> 6;
        const __nv_bfloat16* src = g_Zbf + (size_t)(b * NTOK + r * 64 + s) * 1536
                                   + part * 768 + c0 + nh * 64 + kc * 8;
        cp_async16(sbB + nh * 16384 + SWZ128(krow * 128 + kc * 16), src);
    }
    CP_COMMIT();
    CP_WAIT0();
    __syncthreads();

    int l7 = lane & 7, sel = lane >> 3;
    int rsel = (sel & 1) * 8;
    int csel = (sel >> 1) * 16;
    int g1 = (lane >> 3) & 1;        // trans-ldm row-half selector
    int g2 = (lane >> 4) * 16;       // trans-ldm col byte selector

    float acc[2][8][4];
#pragma unroll
    for (int i = 0; i < 2; i++)
#pragma unroll
        for (int j = 0; j < 8; j++)
#pragma unroll
            for (int v = 0; v < 4; v++) acc[i][j][v] = 0.f;

#pragma unroll
    for (int ks = 0; ks < 12; ks++) {
        int achunk = (ks < 8) ? 0 : 1;
        int akb = (ks & 3) * 32;     // byte offset within chunk row
        int brow = (ks < 4) ? ks * 16 : (ks < 8) ? 64 + (ks - 4) * 16 : (ks - 8) * 16;

        uint32_t afrag[2][4];
#pragma unroll
        for (int mt = 0; mt < 2; mt++) {
            int row = wm * 32 + mt * 16 + l7 + rsel;
            ldmx4(afrag[mt], sbA + achunk * 16384 + SWZ128(row * 128 + akb + csel));
        }
#pragma unroll
        for (int ng = 0; ng < 4; ng++) {
            uint32_t bfrag[4];
            int row = brow + l7 + g1 * 8;
            int colb = ng * 32 + g2;
            ldmx4t(bfrag, sbB + wn * 16384 + SWZ128(row * 128 + colb));
#pragma unroll
            for (int mt = 0; mt < 2; mt++) {
                mma16816(acc[mt][ng * 2 + 0], afrag[mt], bfrag[0], bfrag[1]);
                mma16816(acc[mt][ng * 2 + 1], afrag[mt], bfrag[2], bfrag[3]);
            }
        }
    }

    int rq = lane >> 2, cq = (lane & 3) * 2;
#pragma unroll
    for (int mt = 0; mt < 2; mt++) {
        int ibase = wm * 32 + mt * 16;
#pragma unroll
        for (int n8 = 0; n8 < 8; n8++) {
            float* d = acc[mt][n8];
            int ch = c0 + wn * 64 + n8 * 8 + cq;
            int i0 = ibase + rq, i1 = ibase + rq + 8;
            int q0 = i0 & 63, q1 = i1 & 63;
            int k0 = (i0 < 64) ? r : 64 + r;
            int k1 = (i1 < 64) ? r : 64 + r;
            size_t row0 = ((size_t)(b * 64 + q0) * 128 + k0);
            size_t row1 = ((size_t)(b * 64 + q1) * 128 + k1);
            store_split(g_Ubf + row0 * 1536 + ch, d[0], d[1]);
            store_split(g_Ubf + row1 * 1536 + ch, d[2], d[3]);
        }
    }
}

// ---------------------------------------------------------------------------
// 5) Pass 2 (mma): per (b, q, chtile): out[64p x 128ch] = T2 * V + bias
//    K logical 384: t0 Th*Vh (ks0..7), t1 Th*Vl (8..15), t2 Tl*Vh (16..23)
//    smem: A [4 chunk][64][64] (32KB), B [2 nh][256 krow][64] (64KB)
//    warps 2m x 4n, warp tile 32m x 32n
// ---------------------------------------------------------------------------
__global__ __launch_bounds__(256) void pass2_kernel(
    const float* __restrict__ bias, float* __restrict__ out)
{
    extern __shared__ char smem[];
    uint32_t sb = smem_u32(smem);
    uint32_t sbA = sb, sbB = sb + 32768;
    int b = blockIdx.z, q = blockIdx.y, c0 = blockIdx.x * 128;
    int tid = threadIdx.x;
    int wid = tid >> 5, lane = tid & 31;
    int wm = wid >> 2, wn = wid & 3;

    // load A (32KB linear)
#pragma unroll
    for (int c = 0; c < 8; c++) {
        int o = (tid + c * 256) * 16;
        cp_async16(sbA + SWZ128(o), (const char*)g_T2bf + o);
    }
    // load B (64KB)
#pragma unroll
    for (int c = 0; c < 16; c++) {
        int idx = tid + c * 256;                // 0..4095
        int nh = idx >> 11;
        int rem = idx & 2047;
        int krow = rem >> 3, kc = rem & 7;
        int k = krow & 127, part = krow >> 7;
        const __nv_bfloat16* src = g_Ubf + ((size_t)(b * 64 + q) * 128 + k) * 1536
                                   + part * 768 + c0 + nh * 64 + kc * 8;
        cp_async16(sbB + nh * 32768 + SWZ128(krow * 128 + kc * 16), src);
    }
    CP_COMMIT();
    CP_WAIT0();
    __syncthreads();

    int l7 = lane & 7, sel = lane >> 3;
    int rsel = (sel & 1) * 8;
    int csel = (sel >> 1) * 16;
    int g1 = (lane >> 3) & 1;
    int g2 = (lane >> 4) * 16;

    float acc[2][4][4];
#pragma unroll
    for (int i = 0; i < 2; i++)
#pragma unroll
        for (int j = 0; j < 4; j++)
#pragma unroll
            for (int v = 0; v < 4; v++) acc[i][j][v] = 0.f;

    int nhalf = wn >> 1;
    int nsub = (wn & 1) * 64;        // byte offset of 32-n subtile within half

#pragma unroll
    for (int ks = 0; ks < 24; ks++) {
        int t = ks >> 3;
        int achunk = ((ks & 7) >> 2) + ((t == 2) ? 2 : 0);
        int akb = (ks & 3) * 32;
        int brow = ((t == 1) ? 128 : 0) + (ks & 7) * 16;

        uint32_t afrag[2][4];
#pragma unroll
        for (int mt = 0; mt < 2; mt++) {
            int row = wm * 32 + mt * 16 + l7 + rsel;
            ldmx4(afrag[mt], sbA + achunk * 8192 + SWZ128(row * 128 + akb + csel));
        }
#pragma unroll
        for (int ng = 0; ng < 2; ng++) {
            uint32_t bfrag[4];
            int row = brow + l7 + g1 * 8;
            int colb = nsub + ng * 32 + g2;
            ldmx4t(bfrag, sbB + nhalf * 32768 + SWZ128(row * 128 + colb));
#pragma unroll
            for (int mt = 0; mt < 2; mt++) {
                mma16816(acc[mt][ng * 2 + 0], afrag[mt], bfrag[0], bfrag[1]);
                mma16816(acc[mt][ng * 2 + 1], afrag[mt], bfrag[2], bfrag[3]);
            }
        }
    }

    int rq = lane >> 2, cq = (lane & 3) * 2;
#pragma unroll
    for (int mt = 0; mt < 2; mt++) {
        int pbase = wm * 32 + mt * 16;
#pragma unroll
        for (int n8 = 0; n8 < 4; n8++) {
            float* d = acc[mt][n8];
            int ch = c0 + wn * 32 + n8 * 8 + cq;
            float2 bv = *(const float2*)(bias + ch);
            int p0 = pbase + rq, p1 = pbase + rq + 8;
            float* o0 = out + ((size_t)b * NTOK + p0 * 64 + q) * CDIM + ch;
            float* o1 = out + ((size_t)b * NTOK + p1 * 64 + q) * CDIM + ch;
            *(float2*)o0 = make_float2(d[0] + bv.x, d[1] + bv.y);
            *(float2*)o1 = make_float2(d[2] + bv.x, d[3] + bv.y);
        }
    }
}

// ---------------------------------------------------------------------------
// launch
// ---------------------------------------------------------------------------
extern "C" void kernel_launch(void* const* d_in, const int* in_sizes, int n_in,
                              void* d_out, int out_size)
{
    const float* x      = (const float*)d_in[0];   // [8,4096,768]
    const float* qkv_w  = (const float*)d_in[1];   // [2304,768]
    const float* proj_w = (const float*)d_in[2];   // [768,768]
    const float* proj_b = (const float*)d_in[3];   // [768]
    float* out = (float*)d_out;

    cudaFuncSetAttribute(gemm_mma_kernel, cudaFuncAttributeMaxDynamicSharedMemorySize, 2 * STG_BYTES);
    cudaFuncSetAttribute(pass1_kernel,    cudaFuncAttributeMaxDynamicSharedMemorySize, 65536);
    cudaFuncSetAttribute(pass2_kernel,    cudaFuncAttributeMaxDynamicSharedMemorySize, 98304);

    init_tables_kernel<<<1, 256>>>();
    compute_M_kernel<<<dim3(CDIM / 16, CDIM / 16), dim3(16, 16)>>>(qkv_w, proj_w);
    prep_b_kernel<<<dim3(CDIM / 32, CDIM / 32), 256>>>();
    prep_a_kernel<<<(int)(((size_t)BATCH * NTOK * CDIM / 4 + 255) / 256), 256>>>(x);
    gemm_mma_kernel<<<dim3(CDIM / 128, (BATCH * NTOK) / 128), 256, 2 * STG_BYTES>>>();
    pass1_kernel<<<dim3(CDIM / 128, 64, BATCH), 256, 65536>>>();
    pass2_kernel<<<dim3(CDIM / 128, 64, BATCH), 256, 98304>>>(proj_b, out);
}

// round 9
// speedup vs baseline: 3.6465x; 1.2739x over previous
#include <cuda_runtime.h>
#include <cuda_bf16.h>
#include <cuda_fp16.h>
#include <cstdint>
#include <math.h>

// Problem constants
#define BATCH 8
#define NTOK  4096
#define CDIM  768

// ---------------------------------------------------------------------------
// device scratch (no runtime allocation allowed)
// ---------------------------------------------------------------------------
__device__ float g_M[CDIM * CDIM];                                   // fused weight [c][d]
__device__ __align__(16) __half g_Ah[(size_t)BATCH * NTOK * CDIM];   // [32768][768] fp16 x
__device__ __align__(16) __half g_Bh[(size_t)CDIM * CDIM];           // [768 n][768 k] fp16 M^T
__device__ __align__(16) __nv_bfloat16 g_Zbf[(size_t)BATCH * NTOK * 2 * CDIM]; // [32768][1536]: [Zh|Zl]
__device__ __align__(16) __nv_bfloat16 g_Ubf[(size_t)BATCH * 64 * 128 * 2 * CDIM]; // [(b,q,k)][1536]
__device__ __align__(16) __nv_bfloat16 g_T1bf[2 * 128 * 64];         // [chunk][i][s]  chunk0=hi, 1=lo
__device__ __align__(16) __nv_bfloat16 g_T2bf[4 * 64 * 64];          // [chunk][p][kk]

// ---------------------------------------------------------------------------
// PTX helpers (baseline compute_103-safe)
// ---------------------------------------------------------------------------
__device__ __forceinline__ uint32_t smem_u32(const void* p) {
    uint32_t a;
    asm("{ .reg .u64 t; cvta.to.shared.u64 t, %1; cvt.u32.u64 %0, t; }" : "=r"(a) : "l"(p));
    return a;
}
__device__ __forceinline__ void cp_async16(uint32_t sa, const void* ga) {
    asm volatile("cp.async.cg.shared.global [%0], [%1], 16;" :: "r"(sa), "l"(ga));
}
#define CP_COMMIT() asm volatile("cp.async.commit_group;" ::: "memory")
#define CP_WAIT2()  asm volatile("cp.async.wait_group 2;" ::: "memory")
#define CP_WAIT0()  asm volatile("cp.async.wait_group 0;" ::: "memory")
#define SWZ128(o)   ((o) ^ (((o) >> 3) & 0x70))

__device__ __forceinline__ void ldmx4(uint32_t* r, uint32_t addr) {
    asm volatile("ldmatrix.sync.aligned.m8n8.x4.shared.b16 {%0,%1,%2,%3}, [%4];"
                 : "=r"(r[0]), "=r"(r[1]), "=r"(r[2]), "=r"(r[3]) : "r"(addr));
}
__device__ __forceinline__ void ldmx4t(uint32_t* r, uint32_t addr) {
    asm volatile("ldmatrix.sync.aligned.m8n8.x4.trans.shared.b16 {%0,%1,%2,%3}, [%4];"
                 : "=r"(r[0]), "=r"(r[1]), "=r"(r[2]), "=r"(r[3]) : "r"(addr));
}
__device__ __forceinline__ void mma16816(float* d, const uint32_t* a, uint32_t b0, uint32_t b1) {
    asm volatile("mma.sync.aligned.m16n8k16.row.col.f32.bf16.bf16.f32 "
                 "{%0,%1,%2,%3},{%4,%5,%6,%7},{%8,%9},{%0,%1,%2,%3};"
                 : "+f"(d[0]), "+f"(d[1]), "+f"(d[2]), "+f"(d[3])
                 : "r"(a[0]), "r"(a[1]), "r"(a[2]), "r"(a[3]), "r"(b0), "r"(b1));
}
__device__ __forceinline__ void mma16816h(float* d, const uint32_t* a, uint32_t b0, uint32_t b1) {
    asm volatile("mma.sync.aligned.m16n8k16.row.col.f32.f16.f16.f32 "
                 "{%0,%1,%2,%3},{%4,%5,%6,%7},{%8,%9},{%0,%1,%2,%3};"
                 : "+f"(d[0]), "+f"(d[1]), "+f"(d[2]), "+f"(d[3])
                 : "r"(a[0]), "r"(a[1]), "r"(a[2]), "r"(a[3]), "r"(b0), "r"(b1));
}
// write (a,b) as bf16x2 hi at p, bf16x2 lo at p+768
__device__ __forceinline__ void store_split(__nv_bfloat16* p, float a, float b) {
    __nv_bfloat16 ha = __float2bfloat16(a), hb = __float2bfloat16(b);
    __nv_bfloat162 h; h.x = ha; h.y = hb;
    *(__nv_bfloat162*)p = h;
    __nv_bfloat162 l;
    l.x = __float2bfloat16(a - __bfloat162float(ha));
    l.y = __float2bfloat16(b - __bfloat162float(hb));
    *(__nv_bfloat162*)(p + 768) = l;
}

// ---------------------------------------------------------------------------
// 0) twiddle tables (bf16 hi/lo split)
// ---------------------------------------------------------------------------
__global__ void init_tables_kernel() {
    int tid = threadIdx.x;
    const double TWO_PI = 6.283185307179586476925286766559;
    for (int i = tid; i < 128 * 64; i += 256) {
        int row = i >> 6, s = i & 63;
        double ang = TWO_PI * (double)(((row & 63) * s) & 63) / 64.0;
        float v = (row < 64) ? (float)cos(ang) : (float)sin(ang);
        __nv_bfloat16 h = __float2bfloat16(v);
        g_T1bf[i] = h;
        g_T1bf[128 * 64 + i] = __float2bfloat16(v - __bfloat162float(h));
    }
    for (int i = tid; i < 64 * 128; i += 256) {
        int p = i >> 7, k = i & 127;
        double ang = TWO_PI * (double)((p * (k & 63)) & 63) / 64.0;
        float v = (k < 64) ? (float)cos(ang) : (float)(-sin(ang));
        __nv_bfloat16 h = __float2bfloat16(v);
        int chunk = k >> 6, kk = k & 63;
        g_T2bf[chunk * 4096 + p * 64 + kk] = h;
        g_T2bf[(2 + chunk) * 4096 + p * 64 + kk] = __float2bfloat16(v - __bfloat162float(h));
    }
}

// ---------------------------------------------------------------------------
// 1) M[c][d] = sum_j qkv_w[2C + j, c] * proj_w[d, j]
// ---------------------------------------------------------------------------
__global__ __launch_bounds__(256) void compute_M_kernel(
    const float* __restrict__ qkv_w, const float* __restrict__ proj_w)
{
    __shared__ float sA[16][17];
    __shared__ float sB[16][17];
    int tx = threadIdx.x, ty = threadIdx.y;
    int c0 = blockIdx.y * 16, d0 = blockIdx.x * 16;
    float acc = 0.f;
    for (int j0 = 0; j0 < CDIM; j0 += 16) {
        sA[ty][tx] = qkv_w[(size_t)(2 * CDIM + j0 + ty) * CDIM + c0 + tx];
        sB[tx][ty] = proj_w[(size_t)(d0 + ty) * CDIM + j0 + tx];
        __syncthreads();
#pragma unroll
        for (int jj = 0; jj < 16; jj++)
            acc += sA[jj][ty] * sB[jj][tx];
        __syncthreads();
    }
    g_M[(size_t)(c0 + ty) * CDIM + d0 + tx] = acc;
}

// ---------------------------------------------------------------------------
// 2a) x -> fp16, vectorized: 8 floats -> 8 halves (16B store) per thread
// ---------------------------------------------------------------------------
__global__ __launch_bounds__(256) void prep_a_kernel(const float* __restrict__ x) {
    size_t i8 = ((size_t)blockIdx.x * 256 + threadIdx.x) * 8;
    if (i8 >= (size_t)BATCH * NTOK * CDIM) return;
    float4 v0 = *(const float4*)(x + i8);
    float4 v1 = *(const float4*)(x + i8 + 4);
    __half2 h[4];
    h[0] = __floats2half2_rn(v0.x, v0.y);
    h[1] = __floats2half2_rn(v0.z, v0.w);
    h[2] = __floats2half2_rn(v1.x, v1.y);
    h[3] = __floats2half2_rn(v1.z, v1.w);
    *(uint4*)(g_Ah + i8) = *(uint4*)h;
}

// ---------------------------------------------------------------------------
// 2b) B operand: g_Bh[n][k] = fp16(M[k][n])   (tiled transpose)
// ---------------------------------------------------------------------------
__global__ __launch_bounds__(256) void prep_b_kernel() {
    __shared__ float tile[32][33];
    int k0 = blockIdx.x * 32, n0 = blockIdx.y * 32;
    int tx = threadIdx.x & 31, ty = threadIdx.x >> 5;   // 32 x 8
#pragma unroll
    for (int j = 0; j < 4; j++)
        tile[ty + j * 8][tx] = g_M[(size_t)(k0 + ty + j * 8) * CDIM + n0 + tx];
    __syncthreads();
#pragma unroll
    for (int j = 0; j < 4; j++) {
        int n = n0 + ty + j * 8;
        int k = k0 + tx;
        g_Bh[(size_t)n * CDIM + k] = __float2half_rn(tile[tx][ty + j * 8]);
    }
}

// ---------------------------------------------------------------------------
// 3) Z = x @ M via single-pass fp16 mma GEMM; epilogue writes split-bf16 Z
//    CTA 128x128, K-tile 64, 4-stage cp.async ring, 8 warps (4m x 2n)
// ---------------------------------------------------------------------------
#define GM_NT 12
#define STG_BYTES 32768          /* A 16KB + B 16KB per stage */
#define NSTAGE 4

__device__ __forceinline__ void gemm_load_tile(uint32_t sb, int tid, int bm, int bn,
                                               int kt, int slot) {
    int koff = kt * 64;
    uint32_t abase = sb + slot * STG_BYTES;
    uint32_t bbase = abase + 16384;
#pragma unroll
    for (int c = 0; c < 4; c++) {
        int ch = tid + c * 256;               // 0..1023: 128 rows x 8 chunks
        int row = ch >> 3, kc = ch & 7;
        cp_async16(abase + SWZ128(row * 128 + kc * 16),
                   g_Ah + (size_t)(bm + row) * CDIM + koff + kc * 8);
    }
#pragma unroll
    for (int c = 0; c < 4; c++) {
        int ch = tid + c * 256;
        int row = ch >> 3, kc = ch & 7;
        cp_async16(bbase + SWZ128(row * 128 + kc * 16),
                   g_Bh + (size_t)(bn + row) * CDIM + koff + kc * 8);
    }
}

__global__ __launch_bounds__(256) void gemm_mma_kernel() {
    extern __shared__ char smem[];
    uint32_t sb = smem_u32(smem);
    int tid = threadIdx.x;
    int wid = tid >> 5, lane = tid & 31;
    int wm = wid >> 1, wn = wid & 1;
    int bm = blockIdx.y * 128;
    int bn = blockIdx.x * 128;

    int l7 = lane & 7, sel = lane >> 3;
    int rsel = (sel & 1) * 8;
    int csel = (sel >> 1) * 16;

    float acc[2][8][4];
#pragma unroll
    for (int i = 0; i < 2; i++)
#pragma unroll
        for (int j = 0; j < 8; j++)
#pragma unroll
            for (int v = 0; v < 4; v++) acc[i][j][v] = 0.f;

    // prologue: stages 0..2
#pragma unroll
    for (int s = 0; s < NSTAGE - 1; s++) {
        gemm_load_tile(sb, tid, bm, bn, s, s);
        CP_COMMIT();
    }

    for (int kt = 0; kt < GM_NT; kt++) {
        CP_WAIT2();                // tile kt resident (<=2 newer groups pending)
        __syncthreads();           // slot (kt+3)%4 free (all done computing kt-1)

        if (kt + NSTAGE - 1 < GM_NT)
            gemm_load_tile(sb, tid, bm, bn, kt + NSTAGE - 1, (kt + NSTAGE - 1) & (NSTAGE - 1));
        CP_COMMIT();               // commit (possibly empty) group every iter

        uint32_t ab = sb + (kt & (NSTAGE - 1)) * STG_BYTES;
        uint32_t bb = ab + 16384;
#pragma unroll
        for (int ks = 0; ks < 4; ks++) {
            uint32_t afrag[2][4];
#pragma unroll
            for (int mt = 0; mt < 2; mt++) {
                int row = wm * 32 + mt * 16 + l7 + rsel;
                ldmx4(afrag[mt], ab + SWZ128(row * 128 + ks * 32 + csel));
            }
#pragma unroll
            for (int nt = 0; nt < 4; nt++) {
                uint32_t bfrag[4];
                int row = wn * 64 + nt * 16 + l7 + rsel;
                ldmx4(bfrag, bb + SWZ128(row * 128 + ks * 32 + csel));
#pragma unroll
                for (int mt = 0; mt < 2; mt++) {
                    mma16816h(acc[mt][nt * 2 + 0], afrag[mt], bfrag[0], bfrag[2]);
                    mma16816h(acc[mt][nt * 2 + 1], afrag[mt], bfrag[1], bfrag[3]);
                }
            }
        }
    }

    int rq = lane >> 2, cq = (lane & 3) * 2;
#pragma unroll
    for (int mt = 0; mt < 2; mt++) {
#pragma unroll
        for (int n8 = 0; n8 < 8; n8++) {
            float* d = acc[mt][n8];
            size_t r0 = (size_t)bm + wm * 32 + mt * 16 + rq;
            int c = bn + wn * 64 + n8 * 8 + cq;
            store_split(g_Zbf + r0 * 1536 + c, d[0], d[1]);
            store_split(g_Zbf + (r0 + 8) * 1536 + c, d[2], d[3]);
        }
    }
}

// ---------------------------------------------------------------------------
// 4) Pass 1 (mma, split-bf16 3-term): per (b, r, chtile):
//    U[128i x 128ch] = T1 * Z
// ---------------------------------------------------------------------------
__global__ __launch_bounds__(256) void pass1_kernel() {
    extern __shared__ char smem[];
    uint32_t sb = smem_u32(smem);
    uint32_t sbA = sb, sbB = sb + 32768;
    int b = blockIdx.z, r = blockIdx.y, c0 = blockIdx.x * 128;
    int tid = threadIdx.x;
    int wid = tid >> 5, lane = tid & 31;
    int wm = wid >> 1, wn = wid & 1;

#pragma unroll
    for (int c = 0; c < 8; c++) {
        int o = (tid + c * 256) * 16;
        cp_async16(sbA + SWZ128(o), (const char*)g_T1bf + o);
    }
#pragma unroll
    for (int c = 0; c < 8; c++) {
        int idx = tid + c * 256;
        int nh = idx >> 10;
        int rem = idx & 1023;
        int krow = rem >> 3, kc = rem & 7;
        int s = krow & 63, part = krow >> 6;
        const __nv_bfloat16* src = g_Zbf + (size_t)(b * NTOK + r * 64 + s) * 1536
                                   + part * 768 + c0 + nh * 64 + kc * 8;
        cp_async16(sbB + nh * 16384 + SWZ128(krow * 128 + kc * 16), src);
    }
    CP_COMMIT();
    CP_WAIT0();
    __syncthreads();

    int l7 = lane & 7, sel = lane >> 3;
    int rsel = (sel & 1) * 8;
    int csel = (sel >> 1) * 16;
    int g1 = (lane >> 3) & 1;
    int g2 = (lane >> 4) * 16;

    float acc[2][8][4];
#pragma unroll
    for (int i = 0; i < 2; i++)
#pragma unroll
        for (int j = 0; j < 8; j++)
#pragma unroll
            for (int v = 0; v < 4; v++) acc[i][j][v] = 0.f;

#pragma unroll
    for (int ks = 0; ks < 12; ks++) {
        int achunk = (ks < 8) ? 0 : 1;
        int akb = (ks & 3) * 32;
        int brow = (ks < 4) ? ks * 16 : (ks < 8) ? 64 + (ks - 4) * 16 : (ks - 8) * 16;

        uint32_t afrag[2][4];
#pragma unroll
        for (int mt = 0; mt < 2; mt++) {
            int row = wm * 32 + mt * 16 + l7 + rsel;
            ldmx4(afrag[mt], sbA + achunk * 16384 + SWZ128(row * 128 + akb + csel));
        }
#pragma unroll
        for (int ng = 0; ng < 4; ng++) {
            uint32_t bfrag[4];
            int row = brow + l7 + g1 * 8;
            int colb = ng * 32 + g2;
            ldmx4t(bfrag, sbB + wn * 16384 + SWZ128(row * 128 + colb));
#pragma unroll
            for (int mt = 0; mt < 2; mt++) {
                mma16816(acc[mt][ng * 2 + 0], afrag[mt], bfrag[0], bfrag[1]);
                mma16816(acc[mt][ng * 2 + 1], afrag[mt], bfrag[2], bfrag[3]);
            }
        }
    }

    int rq = lane >> 2, cq = (lane & 3) * 2;
#pragma unroll
    for (int mt = 0; mt < 2; mt++) {
        int ibase = wm * 32 + mt * 16;
#pragma unroll
        for (int n8 = 0; n8 < 8; n8++) {
            float* d = acc[mt][n8];
            int ch = c0 + wn * 64 + n8 * 8 + cq;
            int i0 = ibase + rq, i1 = ibase + rq + 8;
            int q0 = i0 & 63, q1 = i1 & 63;
            int k0 = (i0 < 64) ? r : 64 + r;
            int k1 = (i1 < 64) ? r : 64 + r;
            size_t row0 = ((size_t)(b * 64 + q0) * 128 + k0);
            size_t row1 = ((size_t)(b * 64 + q1) * 128 + k1);
            store_split(g_Ubf + row0 * 1536 + ch, d[0], d[1]);
            store_split(g_Ubf + row1 * 1536 + ch, d[2], d[3]);
        }
    }
}

// ---------------------------------------------------------------------------
// 5) Pass 2 (mma, split-bf16 3-term): per (b, q, chtile):
//    out[64p x 128ch] = T2 * V + bias
// ---------------------------------------------------------------------------
__global__ __launch_bounds__(256) void pass2_kernel(
    const float* __restrict__ bias, float* __restrict__ out)
{
    extern __shared__ char smem[];
    uint32_t sb = smem_u32(smem);
    uint32_t sbA = sb, sbB = sb + 32768;
    int b = blockIdx.z, q = blockIdx.y, c0 = blockIdx.x * 128;
    int tid = threadIdx.x;
    int wid = tid >> 5, lane = tid & 31;
    int wm = wid >> 2, wn = wid & 3;

#pragma unroll
    for (int c = 0; c < 8; c++) {
        int o = (tid + c * 256) * 16;
        cp_async16(sbA + SWZ128(o), (const char*)g_T2bf + o);
    }
#pragma unroll
    for (int c = 0; c < 16; c++) {
        int idx = tid + c * 256;
        int nh = idx >> 11;
        int rem = idx & 2047;
        int krow = rem >> 3, kc = rem & 7;
        int k = krow & 127, part = krow >> 7;
        const __nv_bfloat16* src = g_Ubf + ((size_t)(b * 64 + q) * 128 + k) * 1536
                                   + part * 768 + c0 + nh * 64 + kc * 8;
        cp_async16(sbB + nh * 32768 + SWZ128(krow * 128 + kc * 16), src);
    }
    CP_COMMIT();
    CP_WAIT0();
    __syncthreads();

    int l7 = lane & 7, sel = lane >> 3;
    int rsel = (sel & 1) * 8;
    int csel = (sel >> 1) * 16;
    int g1 = (lane >> 3) & 1;
    int g2 = (lane >> 4) * 16;

    float acc[2][4][4];
#pragma unroll
    for (int i = 0; i < 2; i++)
#pragma unroll
        for (int j = 0; j < 4; j++)
#pragma unroll
            for (int v = 0; v < 4; v++) acc[i][j][v] = 0.f;

    int nhalf = wn >> 1;
    int nsub = (wn & 1) * 64;

#pragma unroll
    for (int ks = 0; ks < 24; ks++) {
        int t = ks >> 3;
        int achunk = ((ks & 7) >> 2) + ((t == 2) ? 2 : 0);
        int akb = (ks & 3) * 32;
        int brow = ((t == 1) ? 128 : 0) + (ks & 7) * 16;

        uint32_t afrag[2][4];
#pragma unroll
        for (int mt = 0; mt < 2; mt++) {
            int row = wm * 32 + mt * 16 + l7 + rsel;
            ldmx4(afrag[mt], sbA + achunk * 8192 + SWZ128(row * 128 + akb + csel));
        }
#pragma unroll
        for (int ng = 0; ng < 2; ng++) {
            uint32_t bfrag[4];
            int row = brow + l7 + g1 * 8;
            int colb = nsub + ng * 32 + g2;
            ldmx4t(bfrag, sbB + nhalf * 32768 + SWZ128(row * 128 + colb));
#pragma unroll
            for (int mt = 0; mt < 2; mt++) {
                mma16816(acc[mt][ng * 2 + 0], afrag[mt], bfrag[0], bfrag[1]);
                mma16816(acc[mt][ng * 2 + 1], afrag[mt], bfrag[2], bfrag[3]);
            }
        }
    }

    int rq = lane >> 2, cq = (lane & 3) * 2;
#pragma unroll
    for (int mt = 0; mt < 2; mt++) {
        int pbase = wm * 32 + mt * 16;
#pragma unroll
        for (int n8 = 0; n8 < 4; n8++) {
            float* d = acc[mt][n8];
            int ch = c0 + wn * 32 + n8 * 8 + cq;
            float2 bv = *(const float2*)(bias + ch);
            int p0 = pbase + rq, p1 = pbase + rq + 8;
            float* o0 = out + ((size_t)b * NTOK + p0 * 64 + q) * CDIM + ch;
            float* o1 = out + ((size_t)b * NTOK + p1 * 64 + q) * CDIM + ch;
            *(float2*)o0 = make_float2(d[0] + bv.x, d[1] + bv.y);
            *(float2*)o1 = make_float2(d[2] + bv.x, d[3] + bv.y);
        }
    }
}

// ---------------------------------------------------------------------------
// launch
// ---------------------------------------------------------------------------
extern "C" void kernel_launch(void* const* d_in, const int* in_sizes, int n_in,
                              void* d_out, int out_size)
{
    const float* x      = (const float*)d_in[0];   // [8,4096,768]
    const float* qkv_w  = (const float*)d_in[1];   // [2304,768]
    const float* proj_w = (const float*)d_in[2];   // [768,768]
    const float* proj_b = (const float*)d_in[3];   // [768]
    float* out = (float*)d_out;

    cudaFuncSetAttribute(gemm_mma_kernel, cudaFuncAttributeMaxDynamicSharedMemorySize, NSTAGE * STG_BYTES);
    cudaFuncSetAttribute(pass1_kernel,    cudaFuncAttributeMaxDynamicSharedMemorySize, 65536);
    cudaFuncSetAttribute(pass2_kernel,    cudaFuncAttributeMaxDynamicSharedMemorySize, 98304);

    init_tables_kernel<<<1, 256>>>();
    compute_M_kernel<<<dim3(CDIM / 16, CDIM / 16), dim3(16, 16)>>>(qkv_w, proj_w);
    prep_b_kernel<<<dim3(CDIM / 32, CDIM / 32), 256>>>();
    prep_a_kernel<<<(int)(((size_t)BATCH * NTOK * CDIM / 8 + 255) / 256), 256>>>(x);
    gemm_mma_kernel<<<dim3(CDIM / 128, (BATCH * NTOK) / 128), 256, NSTAGE * STG_BYTES>>>();
    pass1_kernel<<<dim3(CDIM / 128, 64, BATCH), 256, 65536>>>();
    pass2_kernel<<<dim3(CDIM / 128, 64, BATCH), 256, 98304>>>(proj_b, out);
}

// round 10
// speedup vs baseline: 5.1051x; 1.4000x over previous
#include <cuda_runtime.h>
#include <cuda_bf16.h>
#include <cuda_fp16.h>
#include <cstdint>
#include <math.h>

// Problem constants
#define BATCH 8
#define NTOK  4096
#define CDIM  768

// ---------------------------------------------------------------------------
// device scratch (no runtime allocation allowed)
// ---------------------------------------------------------------------------
__device__ float g_M[CDIM * CDIM];                                   // fused weight [c][d]
__device__ __align__(16) __half g_Ah[(size_t)BATCH * NTOK * CDIM];   // [32768][768] fp16 x
__device__ __align__(16) __half g_Bh[(size_t)CDIM * CDIM];           // [768 n][768 k] fp16 M^T
__device__ __align__(16) __half g_Zh[(size_t)BATCH * NTOK * CDIM];   // [32768][768] fp16 Z
__device__ __align__(16) __half g_Uh[(size_t)BATCH * 64 * 128 * CDIM]; // [(b,q,k)][768] fp16 U
__device__ __align__(16) __half g_T1h[128 * 64];                     // [i][s] i<64: cos(i*s), else sin
__device__ __align__(16) __half g_T2h[64 * 128];                     // [p][k] k<64: cos(p*k), else -sin(p*(k-64))

// ---------------------------------------------------------------------------
// PTX helpers (baseline compute_103-safe)
// ---------------------------------------------------------------------------
__device__ __forceinline__ uint32_t smem_u32(const void* p) {
    uint32_t a;
    asm("{ .reg .u64 t; cvta.to.shared.u64 t, %1; cvt.u32.u64 %0, t; }" : "=r"(a) : "l"(p));
    return a;
}
__device__ __forceinline__ void cp_async16(uint32_t sa, const void* ga) {
    asm volatile("cp.async.cg.shared.global [%0], [%1], 16;" :: "r"(sa), "l"(ga));
}
#define CP_COMMIT() asm volatile("cp.async.commit_group;" ::: "memory")
#define CP_WAIT2()  asm volatile("cp.async.wait_group 2;" ::: "memory")
#define CP_WAIT0()  asm volatile("cp.async.wait_group 0;" ::: "memory")
#define SWZ128(o)   ((o) ^ (((o) >> 3) & 0x70))
#define SWZ256(o)   ((o) ^ (((o) >> 4) & 0x70))   /* for 256B-row tiles */

__device__ __forceinline__ void ldmx4(uint32_t* r, uint32_t addr) {
    asm volatile("ldmatrix.sync.aligned.m8n8.x4.shared.b16 {%0,%1,%2,%3}, [%4];"
                 : "=r"(r[0]), "=r"(r[1]), "=r"(r[2]), "=r"(r[3]) : "r"(addr));
}
__device__ __forceinline__ void ldmx4t(uint32_t* r, uint32_t addr) {
    asm volatile("ldmatrix.sync.aligned.m8n8.x4.trans.shared.b16 {%0,%1,%2,%3}, [%4];"
                 : "=r"(r[0]), "=r"(r[1]), "=r"(r[2]), "=r"(r[3]) : "r"(addr));
}
__device__ __forceinline__ void mma16816h(float* d, const uint32_t* a, uint32_t b0, uint32_t b1) {
    asm volatile("mma.sync.aligned.m16n8k16.row.col.f32.f16.f16.f32 "
                 "{%0,%1,%2,%3},{%4,%5,%6,%7},{%8,%9},{%0,%1,%2,%3};"
                 : "+f"(d[0]), "+f"(d[1]), "+f"(d[2]), "+f"(d[3])
                 : "r"(a[0]), "r"(a[1]), "r"(a[2]), "r"(a[3]), "r"(b0), "r"(b1));
}

#define STG_ROWH 136   /* stage row stride in halves (272B): bank-conflict-free, 16B-aligned */

// ---------------------------------------------------------------------------
// 0) fp16 twiddle tables
// ---------------------------------------------------------------------------
__global__ void init_tables_kernel() {
    int tid = threadIdx.x;
    const double TWO_PI = 6.283185307179586476925286766559;
    for (int i = tid; i < 128 * 64; i += 256) {
        int row = i >> 6, s = i & 63;
        double ang = TWO_PI * (double)(((row & 63) * s) & 63) / 64.0;
        float v = (row < 64) ? (float)cos(ang) : (float)sin(ang);
        g_T1h[i] = __float2half_rn(v);
    }
    for (int i = tid; i < 64 * 128; i += 256) {
        int p = i >> 7, k = i & 127;
        double ang = TWO_PI * (double)((p * (k & 63)) & 63) / 64.0;
        float v = (k < 64) ? (float)cos(ang) : (float)(-sin(ang));
        g_T2h[i] = __float2half_rn(v);
    }
}

// ---------------------------------------------------------------------------
// 1) M[c][d] = sum_j qkv_w[2C + j, c] * proj_w[d, j]
// ---------------------------------------------------------------------------
__global__ __launch_bounds__(256) void compute_M_kernel(
    const float* __restrict__ qkv_w, const float* __restrict__ proj_w)
{
    __shared__ float sA[16][17];
    __shared__ float sB[16][17];
    int tx = threadIdx.x, ty = threadIdx.y;
    int c0 = blockIdx.y * 16, d0 = blockIdx.x * 16;
    float acc = 0.f;
    for (int j0 = 0; j0 < CDIM; j0 += 16) {
        sA[ty][tx] = qkv_w[(size_t)(2 * CDIM + j0 + ty) * CDIM + c0 + tx];
        sB[tx][ty] = proj_w[(size_t)(d0 + ty) * CDIM + j0 + tx];
        __syncthreads();
#pragma unroll
        for (int jj = 0; jj < 16; jj++)
            acc += sA[jj][ty] * sB[jj][tx];
        __syncthreads();
    }
    g_M[(size_t)(c0 + ty) * CDIM + d0 + tx] = acc;
}

// ---------------------------------------------------------------------------
// 2a) x -> fp16 (8 floats -> 16B store per thread)
// ---------------------------------------------------------------------------
__global__ __launch_bounds__(256) void prep_a_kernel(const float* __restrict__ x) {
    size_t i8 = ((size_t)blockIdx.x * 256 + threadIdx.x) * 8;
    if (i8 >= (size_t)BATCH * NTOK * CDIM) return;
    float4 v0 = *(const float4*)(x + i8);
    float4 v1 = *(const float4*)(x + i8 + 4);
    __half2 h[4];
    h[0] = __floats2half2_rn(v0.x, v0.y);
    h[1] = __floats2half2_rn(v0.z, v0.w);
    h[2] = __floats2half2_rn(v1.x, v1.y);
    h[3] = __floats2half2_rn(v1.z, v1.w);
    *(uint4*)(g_Ah + i8) = *(uint4*)h;
}

// ---------------------------------------------------------------------------
// 2b) B operand: g_Bh[n][k] = fp16(M[k][n])   (tiled transpose)
// ---------------------------------------------------------------------------
__global__ __launch_bounds__(256) void prep_b_kernel() {
    __shared__ float tile[32][33];
    int k0 = blockIdx.x * 32, n0 = blockIdx.y * 32;
    int tx = threadIdx.x & 31, ty = threadIdx.x >> 5;
#pragma unroll
    for (int j = 0; j < 4; j++)
        tile[ty + j * 8][tx] = g_M[(size_t)(k0 + ty + j * 8) * CDIM + n0 + tx];
    __syncthreads();
#pragma unroll
    for (int j = 0; j < 4; j++) {
        int n = n0 + ty + j * 8;
        int k = k0 + tx;
        g_Bh[(size_t)n * CDIM + k] = __float2half_rn(tile[tx][ty + j * 8]);
    }
}

// ---------------------------------------------------------------------------
// 3) Z = x @ M, fp16 mma GEMM, CTA 128x128, K-tile 64, 4-stage cp.async ring
//    epilogue: stage fp16 in smem -> coalesced 16B stores
// ---------------------------------------------------------------------------
#define GM_NT 12
#define STG_BYTES 32768
#define NSTAGE 4

__device__ __forceinline__ void gemm_load_tile(uint32_t sb, int tid, int bm, int bn,
                                               int kt, int slot) {
    int koff = kt * 64;
    uint32_t abase = sb + slot * STG_BYTES;
    uint32_t bbase = abase + 16384;
#pragma unroll
    for (int c = 0; c < 4; c++) {
        int ch = tid + c * 256;
        int row = ch >> 3, kc = ch & 7;
        cp_async16(abase + SWZ128(row * 128 + kc * 16),
                   g_Ah + (size_t)(bm + row) * CDIM + koff + kc * 8);
    }
#pragma unroll
    for (int c = 0; c < 4; c++) {
        int ch = tid + c * 256;
        int row = ch >> 3, kc = ch & 7;
        cp_async16(bbase + SWZ128(row * 128 + kc * 16),
                   g_Bh + (size_t)(bn + row) * CDIM + koff + kc * 8);
    }
}

__global__ __launch_bounds__(256) void gemm_mma_kernel() {
    extern __shared__ char smem[];
    uint32_t sb = smem_u32(smem);
    __half* stage = (__half*)smem;
    int tid = threadIdx.x;
    int wid = tid >> 5, lane = tid & 31;
    int wm = wid >> 1, wn = wid & 1;
    int bm = blockIdx.y * 128;
    int bn = blockIdx.x * 128;

    int l7 = lane & 7, sel = lane >> 3;
    int rsel = (sel & 1) * 8;
    int csel = (sel >> 1) * 16;

    float acc[2][8][4];
#pragma unroll
    for (int i = 0; i < 2; i++)
#pragma unroll
        for (int j = 0; j < 8; j++)
#pragma unroll
            for (int v = 0; v < 4; v++) acc[i][j][v] = 0.f;

#pragma unroll
    for (int s = 0; s < NSTAGE - 1; s++) {
        gemm_load_tile(sb, tid, bm, bn, s, s);
        CP_COMMIT();
    }

    for (int kt = 0; kt < GM_NT; kt++) {
        CP_WAIT2();
        __syncthreads();

        if (kt + NSTAGE - 1 < GM_NT)
            gemm_load_tile(sb, tid, bm, bn, kt + NSTAGE - 1, (kt + NSTAGE - 1) & (NSTAGE - 1));
        CP_COMMIT();

        uint32_t ab = sb + (kt & (NSTAGE - 1)) * STG_BYTES;
        uint32_t bb = ab + 16384;
#pragma unroll
        for (int ks = 0; ks < 4; ks++) {
            uint32_t afrag[2][4];
#pragma unroll
            for (int mt = 0; mt < 2; mt++) {
                int row = wm * 32 + mt * 16 + l7 + rsel;
                ldmx4(afrag[mt], ab + SWZ128(row * 128 + ks * 32 + csel));
            }
#pragma unroll
            for (int nt = 0; nt < 4; nt++) {
                uint32_t bfrag[4];
                int row = wn * 64 + nt * 16 + l7 + rsel;
                ldmx4(bfrag, bb + SWZ128(row * 128 + ks * 32 + csel));
#pragma unroll
                for (int mt = 0; mt < 2; mt++) {
                    mma16816h(acc[mt][nt * 2 + 0], afrag[mt], bfrag[0], bfrag[2]);
                    mma16816h(acc[mt][nt * 2 + 1], afrag[mt], bfrag[1], bfrag[3]);
                }
            }
        }
    }

    // epilogue: stage fp16 -> coalesced stores
    __syncthreads();
    int rq = lane >> 2, cq = (lane & 3) * 2;
#pragma unroll
    for (int mt = 0; mt < 2; mt++) {
#pragma unroll
        for (int n8 = 0; n8 < 8; n8++) {
            float* d = acc[mt][n8];
            int r0 = wm * 32 + mt * 16 + rq;
            int c = wn * 64 + n8 * 8 + cq;
            *(__half2*)&stage[r0 * STG_ROWH + c] = __floats2half2_rn(d[0], d[1]);
            *(__half2*)&stage[(r0 + 8) * STG_ROWH + c] = __floats2half2_rn(d[2], d[3]);
        }
    }
    __syncthreads();
#pragma unroll
    for (int it = 0; it < 8; it++) {
        int idx = tid + it * 256;                 // 0..2047
        int row = idx >> 4, ck = idx & 15;
        uint4 v = *(uint4*)&stage[row * STG_ROWH + ck * 8];
        *(uint4*)(g_Zh + (size_t)(bm + row) * CDIM + bn + ck * 8) = v;
    }
}

// ---------------------------------------------------------------------------
// 4) Pass 1 (fp16 mma): per (b, r, chtile): U[128i x 128ch] = T1 * Z[64s x 128ch]
//    A 16KB (128B rows, SWZ128), B 16KB (256B rows, SWZ256); staged epilogue.
// ---------------------------------------------------------------------------
#define P1_SMEM (128 * STG_ROWH * 2 + 256)   /* stage 34816B, overlays A+B */

__global__ __launch_bounds__(256) void pass1_kernel() {
    extern __shared__ char smem[];
    uint32_t sb = smem_u32(smem);
    uint32_t sbA = sb, sbB = sb + 16384;
    __half* stage = (__half*)smem;
    int b = blockIdx.z, r = blockIdx.y, c0 = blockIdx.x * 128;
    int tid = threadIdx.x;
    int wid = tid >> 5, lane = tid & 31;
    int wm = wid >> 1, wn = wid & 1;

    // load A = T1h [128 i][64 s] (16KB, 128B rows)
#pragma unroll
    for (int c = 0; c < 4; c++) {
        int idx = tid + c * 256;                 // 0..1023
        int row = idx >> 3, kc = idx & 7;
        cp_async16(sbA + SWZ128(row * 128 + kc * 16), g_T1h + row * 64 + kc * 8);
    }
    // load B = Z [64 s][128 ch] (16KB, 256B rows)
#pragma unroll
    for (int c = 0; c < 4; c++) {
        int idx = tid + c * 256;                 // 0..1023
        int s = idx >> 4, ck = idx & 15;
        cp_async16(sbB + SWZ256(s * 256 + ck * 16),
                   g_Zh + (size_t)(b * NTOK + r * 64 + s) * CDIM + c0 + ck * 8);
    }
    CP_COMMIT();
    CP_WAIT0();
    __syncthreads();

    int l7 = lane & 7, sel = lane >> 3;
    int rsel = (sel & 1) * 8;
    int csel = (sel >> 1) * 16;
    int g1 = (lane >> 3) & 1;
    int g2 = (lane >> 4) * 16;

    float acc[2][8][4];
#pragma unroll
    for (int i = 0; i < 2; i++)
#pragma unroll
        for (int j = 0; j < 8; j++)
#pragma unroll
            for (int v = 0; v < 4; v++) acc[i][j][v] = 0.f;

#pragma unroll
    for (int ks = 0; ks < 4; ks++) {
        uint32_t afrag[2][4];
#pragma unroll
        for (int mt = 0; mt < 2; mt++) {
            int row = wm * 32 + mt * 16 + l7 + rsel;
            ldmx4(afrag[mt], sbA + SWZ128(row * 128 + ks * 32 + csel));
        }
#pragma unroll
        for (int ng = 0; ng < 4; ng++) {
            uint32_t bfrag[4];
            int row = ks * 16 + l7 + g1 * 8;
            int colb = wn * 64 + ng * 16;        // 8-ch pairs: ng covers 16 bytes? (see mapping)
            // B warp tile: wn selects 64 ch (128 bytes); ng covers 32B (16 ch)
            colb = wn * 128 + ng * 32 + g2;
            ldmx4t(bfrag, sbB + SWZ256(row * 256 + colb));
#pragma unroll
            for (int mt = 0; mt < 2; mt++) {
                mma16816h(acc[mt][ng * 2 + 0], afrag[mt], bfrag[0], bfrag[1]);
                mma16816h(acc[mt][ng * 2 + 1], afrag[mt], bfrag[2], bfrag[3]);
            }
        }
    }

    // stage epilogue
    __syncthreads();
    int rq = lane >> 2, cq = (lane & 3) * 2;
#pragma unroll
    for (int mt = 0; mt < 2; mt++) {
#pragma unroll
        for (int n8 = 0; n8 < 8; n8++) {
            float* d = acc[mt][n8];
            int i0 = wm * 32 + mt * 16 + rq;
            int chl = wn * 64 + n8 * 8 + cq;
            *(__half2*)&stage[i0 * STG_ROWH + chl] = __floats2half2_rn(d[0], d[1]);
            *(__half2*)&stage[(i0 + 8) * STG_ROWH + chl] = __floats2half2_rn(d[2], d[3]);
        }
    }
    __syncthreads();
#pragma unroll
    for (int it = 0; it < 8; it++) {
        int idx = tid + it * 256;                 // 0..2047
        int row = idx >> 4, ck = idx & 15;
        int q = row & 63;
        int kk = (row < 64) ? r : 64 + r;
        uint4 v = *(uint4*)&stage[row * STG_ROWH + ck * 8];
        *(uint4*)(g_Uh + ((size_t)(b * 64 + q) * 128 + kk) * CDIM + c0 + ck * 8) = v;
    }
}

// ---------------------------------------------------------------------------
// 5) Pass 2 (fp16 mma): per (b, q, chtile): out[64p x 128ch] = T2 * U + bias
//    A = T2h [64p][128k] 16KB (256B rows), B = U [128k][128ch] 32KB (256B rows)
//    warps 2m x 4n; direct fp32 stores (32B segments)
// ---------------------------------------------------------------------------
__global__ __launch_bounds__(256) void pass2_kernel(
    const float* __restrict__ bias, float* __restrict__ out)
{
    extern __shared__ char smem[];
    uint32_t sb = smem_u32(smem);
    uint32_t sbA = sb, sbB = sb + 16384;
    int b = blockIdx.z, q = blockIdx.y, c0 = blockIdx.x * 128;
    int tid = threadIdx.x;
    int wid = tid >> 5, lane = tid & 31;
    int wm = wid >> 2, wn = wid & 3;

    // load A = T2h (16KB)
#pragma unroll
    for (int c = 0; c < 4; c++) {
        int idx = tid + c * 256;                 // 0..1023
        int p = idx >> 4, ck = idx & 15;
        cp_async16(sbA + SWZ256(p * 256 + ck * 16), g_T2h + p * 128 + ck * 8);
    }
    // load B = U (32KB)
#pragma unroll
    for (int c = 0; c < 8; c++) {
        int idx = tid + c * 256;                 // 0..2047
        int k = idx >> 4, ck = idx & 15;
        cp_async16(sbB + SWZ256(k * 256 + ck * 16),
                   g_Uh + ((size_t)(b * 64 + q) * 128 + k) * CDIM + c0 + ck * 8);
    }
    CP_COMMIT();
    CP_WAIT0();
    __syncthreads();

    int l7 = lane & 7, sel = lane >> 3;
    int rsel = (sel & 1) * 8;
    int csel = (sel >> 1) * 16;
    int g1 = (lane >> 3) & 1;
    int g2 = (lane >> 4) * 16;

    float acc[2][4][4];
#pragma unroll
    for (int i = 0; i < 2; i++)
#pragma unroll
        for (int j = 0; j < 4; j++)
#pragma unroll
            for (int v = 0; v < 4; v++) acc[i][j][v] = 0.f;

#pragma unroll
    for (int ks = 0; ks < 8; ks++) {
        uint32_t afrag[2][4];
#pragma unroll
        for (int mt = 0; mt < 2; mt++) {
            int row = wm * 32 + mt * 16 + l7 + rsel;
            ldmx4(afrag[mt], sbA + SWZ256(row * 256 + ks * 32 + csel));
        }
#pragma unroll
        for (int ng = 0; ng < 2; ng++) {
            uint32_t bfrag[4];
            int row = ks * 16 + l7 + g1 * 8;
            int colb = wn * 64 + ng * 32 + g2;   // ch bytes: warp covers 32 ch (64B)
            ldmx4t(bfrag, sbB + SWZ256(row * 256 + colb));
#pragma unroll
            for (int mt = 0; mt < 2; mt++) {
                mma16816h(acc[mt][ng * 2 + 0], afrag[mt], bfrag[0], bfrag[1]);
                mma16816h(acc[mt][ng * 2 + 1], afrag[mt], bfrag[2], bfrag[3]);
            }
        }
    }

    int rq = lane >> 2, cq = (lane & 3) * 2;
#pragma unroll
    for (int mt = 0; mt < 2; mt++) {
        int pbase = wm * 32 + mt * 16;
#pragma unroll
        for (int n8 = 0; n8 < 4; n8++) {
            float* d = acc[mt][n8];
            int ch = c0 + wn * 32 + n8 * 8 + cq;
            float2 bv = *(const float2*)(bias + ch);
            int p0 = pbase + rq, p1 = pbase + rq + 8;
            float* o0 = out + ((size_t)b * NTOK + p0 * 64 + q) * CDIM + ch;
            float* o1 = out + ((size_t)b * NTOK + p1 * 64 + q) * CDIM + ch;
            *(float2*)o0 = make_float2(d[0] + bv.x, d[1] + bv.y);
            *(float2*)o1 = make_float2(d[2] + bv.x, d[3] + bv.y);
        }
    }
}

// ---------------------------------------------------------------------------
// launch
// ---------------------------------------------------------------------------
extern "C" void kernel_launch(void* const* d_in, const int* in_sizes, int n_in,
                              void* d_out, int out_size)
{
    const float* x      = (const float*)d_in[0];   // [8,4096,768]
    const float* qkv_w  = (const float*)d_in[1];   // [2304,768]
    const float* proj_w = (const float*)d_in[2];   // [768,768]
    const float* proj_b = (const float*)d_in[3];   // [768]
    float* out = (float*)d_out;

    cudaFuncSetAttribute(gemm_mma_kernel, cudaFuncAttributeMaxDynamicSharedMemorySize, NSTAGE * STG_BYTES);
    cudaFuncSetAttribute(pass1_kernel,    cudaFuncAttributeMaxDynamicSharedMemorySize, P1_SMEM);
    cudaFuncSetAttribute(pass2_kernel,    cudaFuncAttributeMaxDynamicSharedMemorySize, 49152);

    init_tables_kernel<<<1, 256>>>();
    compute_M_kernel<<<dim3(CDIM / 16, CDIM / 16), dim3(16, 16)>>>(qkv_w, proj_w);
    prep_b_kernel<<<dim3(CDIM / 32, CDIM / 32), 256>>>();
    prep_a_kernel<<<(int)(((size_t)BATCH * NTOK * CDIM / 8 + 255) / 256), 256>>>(x);
    gemm_mma_kernel<<<dim3(CDIM / 128, (BATCH * NTOK) / 128), 256, NSTAGE * STG_BYTES>>>();
    pass1_kernel<<<dim3(CDIM / 128, 64, BATCH), 256, P1_SMEM>>>();
    pass2_kernel<<<dim3(CDIM / 128, 64, BATCH), 256, 49152>>>(proj_b, out);
}

// round 11
// speedup vs baseline: 6.3105x; 1.2361x over previous
#include <cuda_runtime.h>
#include <cuda_bf16.h>
#include <cuda_fp16.h>
#include <cstdint>
#include <math.h>

// Problem constants
#define BATCH 8
#define NTOK  4096
#define CDIM  768

// ---------------------------------------------------------------------------
// device scratch (no runtime allocation allowed)
// ---------------------------------------------------------------------------
__device__ float g_M[CDIM * CDIM];                                   // fused weight [c][d]
__device__ __align__(16) __half g_Ah[(size_t)BATCH * NTOK * CDIM];   // [32768][768] fp16 x
__device__ __align__(16) __half g_Bh[(size_t)CDIM * CDIM];           // [768 n][768 k] fp16 M^T
__device__ __align__(16) __half g_Uh[(size_t)BATCH * 64 * 128 * CDIM]; // [(b,q,k)][768] fp16 U
__device__ __align__(16) __half g_T1h[128 * 64];                     // [i][s] i<64: cos(i*s), else sin
__device__ __align__(16) __half g_T2h[64 * 128];                     // [p][k] k<64: cos(p*k), else -sin

// ---------------------------------------------------------------------------
// PTX helpers (baseline compute_103-safe)
// ---------------------------------------------------------------------------
__device__ __forceinline__ uint32_t smem_u32(const void* p) {
    uint32_t a;
    asm("{ .reg .u64 t; cvta.to.shared.u64 t, %1; cvt.u32.u64 %0, t; }" : "=r"(a) : "l"(p));
    return a;
}
__device__ __forceinline__ void cp_async16(uint32_t sa, const void* ga) {
    asm volatile("cp.async.cg.shared.global [%0], [%1], 16;" :: "r"(sa), "l"(ga));
}
#define CP_COMMIT() asm volatile("cp.async.commit_group;" ::: "memory")
#define CP_WAIT2()  asm volatile("cp.async.wait_group 2;" ::: "memory")
#define CP_WAIT1()  asm volatile("cp.async.wait_group 1;" ::: "memory")
#define CP_WAIT0()  asm volatile("cp.async.wait_group 0;" ::: "memory")
#define SWZ128(o)   ((o) ^ (((o) >> 3) & 0x70))
#define SWZ256(o)   ((o) ^ (((o) >> 4) & 0x70))

__device__ __forceinline__ void ldmx4(uint32_t* r, uint32_t addr) {
    asm volatile("ldmatrix.sync.aligned.m8n8.x4.shared.b16 {%0,%1,%2,%3}, [%4];"
                 : "=r"(r[0]), "=r"(r[1]), "=r"(r[2]), "=r"(r[3]) : "r"(addr));
}
__device__ __forceinline__ void ldmx4t(uint32_t* r, uint32_t addr) {
    asm volatile("ldmatrix.sync.aligned.m8n8.x4.trans.shared.b16 {%0,%1,%2,%3}, [%4];"
                 : "=r"(r[0]), "=r"(r[1]), "=r"(r[2]), "=r"(r[3]) : "r"(addr));
}
__device__ __forceinline__ void mma16816h(float* d, const uint32_t* a, uint32_t b0, uint32_t b1) {
    asm volatile("mma.sync.aligned.m16n8k16.row.col.f32.f16.f16.f32 "
                 "{%0,%1,%2,%3},{%4,%5,%6,%7},{%8,%9},{%0,%1,%2,%3};"
                 : "+f"(d[0]), "+f"(d[1]), "+f"(d[2]), "+f"(d[3])
                 : "r"(a[0]), "r"(a[1]), "r"(a[2]), "r"(a[3]), "r"(b0), "r"(b1));
}

#define STG_ROWH 136   /* stage row stride in halves (272B): conflict-free, 16B-aligned */

// ---------------------------------------------------------------------------
// 0) fp16 twiddle tables
// ---------------------------------------------------------------------------
__global__ void init_tables_kernel() {
    int tid = threadIdx.x;
    const double TWO_PI = 6.283185307179586476925286766559;
    for (int i = tid; i < 128 * 64; i += 256) {
        int row = i >> 6, s = i & 63;
        double ang = TWO_PI * (double)(((row & 63) * s) & 63) / 64.0;
        float v = (row < 64) ? (float)cos(ang) : (float)sin(ang);
        g_T1h[i] = __float2half_rn(v);
    }
    for (int i = tid; i < 64 * 128; i += 256) {
        int p = i >> 7, k = i & 127;
        double ang = TWO_PI * (double)((p * (k & 63)) & 63) / 64.0;
        float v = (k < 64) ? (float)cos(ang) : (float)(-sin(ang));
        g_T2h[i] = __float2half_rn(v);
    }
}

// ---------------------------------------------------------------------------
// 1) M[c][d] = sum_j qkv_w[2C + j, c] * proj_w[d, j]
//    64x64 tile, 4x4 micro, 256 threads
// ---------------------------------------------------------------------------
__global__ __launch_bounds__(256) void compute_M_kernel(
    const float* __restrict__ qkv_w, const float* __restrict__ proj_w)
{
    __shared__ float sA[16][68];   // [kk][mm]  A[m][k] = qkv_w[2C+k][m]
    __shared__ float sB[16][68];   // [kk][nn]  B[k][n] = proj_w[n][k]
    int c0 = blockIdx.y * 64, d0 = blockIdx.x * 64;
    int tid = threadIdx.x;
    int ty = (tid >> 4) << 2, tx = (tid & 15) << 2;
    float acc[4][4];
#pragma unroll
    for (int i = 0; i < 4; i++)
#pragma unroll
        for (int j = 0; j < 4; j++) acc[i][j] = 0.f;

    for (int k0 = 0; k0 < CDIM; k0 += 16) {
        // sA: coalesced over m
#pragma unroll
        for (int c = 0; c < 4; c++) {
            int e = tid + c * 256;             // 0..1023
            int kk = e >> 6, mm = e & 63;
            sA[kk][mm] = qkv_w[(size_t)(2 * CDIM + k0 + kk) * CDIM + c0 + mm];
        }
        // sB: float4 along k (contiguous in proj_w rows)
        {
            int nn = tid >> 2, kq = (tid & 3) * 4;
            float4 v = *(const float4*)(proj_w + (size_t)(d0 + nn) * CDIM + k0 + kq);
            sB[kq + 0][nn] = v.x; sB[kq + 1][nn] = v.y;
            sB[kq + 2][nn] = v.z; sB[kq + 3][nn] = v.w;
        }
        __syncthreads();
#pragma unroll
        for (int kk = 0; kk < 16; kk++) {
            float a[4], b[4];
            *(float4*)a = *(const float4*)&sA[kk][ty];
            *(float4*)b = *(const float4*)&sB[kk][tx];
#pragma unroll
            for (int i = 0; i < 4; i++)
#pragma unroll
                for (int j = 0; j < 4; j++)
                    acc[i][j] += a[i] * b[j];
        }
        __syncthreads();
    }
#pragma unroll
    for (int i = 0; i < 4; i++) {
        float* row = g_M + (size_t)(c0 + ty + i) * CDIM + d0 + tx;
        *(float4*)row = make_float4(acc[i][0], acc[i][1], acc[i][2], acc[i][3]);
    }
}

// ---------------------------------------------------------------------------
// 2a) x -> fp16 (8 floats -> 16B store per thread)
// ---------------------------------------------------------------------------
__global__ __launch_bounds__(256) void prep_a_kernel(const float* __restrict__ x) {
    size_t i8 = ((size_t)blockIdx.x * 256 + threadIdx.x) * 8;
    if (i8 >= (size_t)BATCH * NTOK * CDIM) return;
    float4 v0 = *(const float4*)(x + i8);
    float4 v1 = *(const float4*)(x + i8 + 4);
    __half2 h[4];
    h[0] = __floats2half2_rn(v0.x, v0.y);
    h[1] = __floats2half2_rn(v0.z, v0.w);
    h[2] = __floats2half2_rn(v1.x, v1.y);
    h[3] = __floats2half2_rn(v1.z, v1.w);
    *(uint4*)(g_Ah + i8) = *(uint4*)h;
}

// ---------------------------------------------------------------------------
// 2b) B operand: g_Bh[n][k] = fp16(M[k][n])   (tiled transpose)
// ---------------------------------------------------------------------------
__global__ __launch_bounds__(256) void prep_b_kernel() {
    __shared__ float tile[32][33];
    int k0 = blockIdx.x * 32, n0 = blockIdx.y * 32;
    int tx = threadIdx.x & 31, ty = threadIdx.x >> 5;
#pragma unroll
    for (int j = 0; j < 4; j++)
        tile[ty + j * 8][tx] = g_M[(size_t)(k0 + ty + j * 8) * CDIM + n0 + tx];
    __syncthreads();
#pragma unroll
    for (int j = 0; j < 4; j++) {
        int n = n0 + ty + j * 8;
        int k = k0 + tx;
        g_Bh[(size_t)n * CDIM + k] = __float2half_rn(tile[tx][ty + j * 8]);
    }
}

// ---------------------------------------------------------------------------
// 3) Fused GEMM + pass1:
//    Z_tile = x @ M (fp16 mma, CTA 128x128, K-tile 64, 4-stage ring)
//    then U[128i x 128ch] = T1 * Z for the 2 spatial rows in this tile,
//    written straight to g_Uh. Z never touches global memory.
// ---------------------------------------------------------------------------
#define GM_NT 12
#define STG_BYTES 32768
#define NSTAGE 4
#define GM_SMEM (NSTAGE * STG_BYTES + 16384)   /* + T1 */

__device__ __forceinline__ void gemm_load_tile(uint32_t sb, int tid, int bm, int bn,
                                               int kt, int slot) {
    int koff = kt * 64;
    uint32_t abase = sb + slot * STG_BYTES;
    uint32_t bbase = abase + 16384;
#pragma unroll
    for (int c = 0; c < 4; c++) {
        int ch = tid + c * 256;
        int row = ch >> 3, kc = ch & 7;
        cp_async16(abase + SWZ128(row * 128 + kc * 16),
                   g_Ah + (size_t)(bm + row) * CDIM + koff + kc * 8);
    }
#pragma unroll
    for (int c = 0; c < 4; c++) {
        int ch = tid + c * 256;
        int row = ch >> 3, kc = ch & 7;
        cp_async16(bbase + SWZ128(row * 128 + kc * 16),
                   g_Bh + (size_t)(bn + row) * CDIM + koff + kc * 8);
    }
}

__global__ __launch_bounds__(256) void gemm_mma_kernel() {
    extern __shared__ char smem[];
    uint32_t sb = smem_u32(smem);
    uint32_t sbT1 = sb + NSTAGE * STG_BYTES;
    __half* stage1 = (__half*)smem;                            // Z tile  (34816B)
    __half* stage2 = (__half*)(smem + 128 * STG_ROWH * 2);     // U tile  (34816B)
    uint32_t sbS1 = sb;
    int tid = threadIdx.x;
    int wid = tid >> 5, lane = tid & 31;
    int wm = wid >> 1, wn = wid & 1;
    int bm = blockIdx.y * 128;
    int bn = blockIdx.x * 128;
    int b = bm >> 12;                 // batch
    int r0 = (bm >> 6) & 63;          // first spatial row of this tile

    int l7 = lane & 7, sel = lane >> 3;
    int rsel = (sel & 1) * 8;
    int csel = (sel >> 1) * 16;
    int g1 = (lane >> 3) & 1;
    int g2 = (lane >> 4) * 16;

    float acc[2][8][4];
#pragma unroll
    for (int i = 0; i < 2; i++)
#pragma unroll
        for (int j = 0; j < 8; j++)
#pragma unroll
            for (int v = 0; v < 4; v++) acc[i][j][v] = 0.f;

    // prologue: T1 + tile0 in group 0; tiles 1,2 in groups 1,2
#pragma unroll
    for (int c = 0; c < 4; c++) {
        int o = (tid + c * 256) * 16;       // 0..16383
        cp_async16(sbT1 + SWZ128(o), (const char*)g_T1h + o);
    }
    gemm_load_tile(sb, tid, bm, bn, 0, 0);
    CP_COMMIT();
    gemm_load_tile(sb, tid, bm, bn, 1, 1);
    CP_COMMIT();
    gemm_load_tile(sb, tid, bm, bn, 2, 2);
    CP_COMMIT();

    for (int kt = 0; kt < GM_NT; kt++) {
        CP_WAIT2();
        __syncthreads();

        if (kt + NSTAGE - 1 < GM_NT)
            gemm_load_tile(sb, tid, bm, bn, kt + NSTAGE - 1, (kt + NSTAGE - 1) & (NSTAGE - 1));
        CP_COMMIT();

        uint32_t ab = sb + (kt & (NSTAGE - 1)) * STG_BYTES;
        uint32_t bb = ab + 16384;
#pragma unroll
        for (int ks = 0; ks < 4; ks++) {
            uint32_t afrag[2][4];
#pragma unroll
            for (int mt = 0; mt < 2; mt++) {
                int row = wm * 32 + mt * 16 + l7 + rsel;
                ldmx4(afrag[mt], ab + SWZ128(row * 128 + ks * 32 + csel));
            }
#pragma unroll
            for (int nt = 0; nt < 4; nt++) {
                uint32_t bfrag[4];
                int row = wn * 64 + nt * 16 + l7 + rsel;
                ldmx4(bfrag, bb + SWZ128(row * 128 + ks * 32 + csel));
#pragma unroll
                for (int mt = 0; mt < 2; mt++) {
                    mma16816h(acc[mt][nt * 2 + 0], afrag[mt], bfrag[0], bfrag[2]);
                    mma16816h(acc[mt][nt * 2 + 1], afrag[mt], bfrag[1], bfrag[3]);
                }
            }
        }
    }

    // ---- stage Z (fp16) into stage1 ----
    CP_WAIT0();
    __syncthreads();
    int rq = lane >> 2, cq = (lane & 3) * 2;
#pragma unroll
    for (int mt = 0; mt < 2; mt++) {
#pragma unroll
        for (int n8 = 0; n8 < 8; n8++) {
            float* d = acc[mt][n8];
            int row = wm * 32 + mt * 16 + rq;
            int c = wn * 64 + n8 * 8 + cq;
            *(__half2*)&stage1[row * STG_ROWH + c] = __floats2half2_rn(d[0], d[1]);
            *(__half2*)&stage1[(row + 8) * STG_ROWH + c] = __floats2half2_rn(d[2], d[3]);
        }
    }
    __syncthreads();

    // ---- fused pass1: per half h (spatial row r0+h): U = T1 * Z_h ----
#pragma unroll
    for (int h = 0; h < 2; h++) {
        float uacc[2][8][4];
#pragma unroll
        for (int i = 0; i < 2; i++)
#pragma unroll
            for (int j = 0; j < 8; j++)
#pragma unroll
                for (int v = 0; v < 4; v++) uacc[i][j][v] = 0.f;

#pragma unroll
        for (int ks = 0; ks < 4; ks++) {
            uint32_t afrag[2][4];
#pragma unroll
            for (int mt = 0; mt < 2; mt++) {
                int row = wm * 32 + mt * 16 + l7 + rsel;
                ldmx4(afrag[mt], sbT1 + SWZ128(row * 128 + ks * 32 + csel));
            }
#pragma unroll
            for (int ng = 0; ng < 4; ng++) {
                uint32_t bfrag[4];
                int srow = h * 64 + ks * 16 + l7 + g1 * 8;
                int colb = wn * 128 + ng * 32 + g2;
                ldmx4t(bfrag, sbS1 + srow * (STG_ROWH * 2) + colb);
#pragma unroll
                for (int mt = 0; mt < 2; mt++) {
                    mma16816h(uacc[mt][ng * 2 + 0], afrag[mt], bfrag[0], bfrag[1]);
                    mma16816h(uacc[mt][ng * 2 + 1], afrag[mt], bfrag[2], bfrag[3]);
                }
            }
        }

        // write U frags to stage2, then coalesced store
        if (h == 1) __syncthreads();      // prior stage2 store complete
#pragma unroll
        for (int mt = 0; mt < 2; mt++) {
#pragma unroll
            for (int n8 = 0; n8 < 8; n8++) {
                float* d = uacc[mt][n8];
                int i0 = wm * 32 + mt * 16 + rq;
                int chl = wn * 64 + n8 * 8 + cq;
                *(__half2*)&stage2[i0 * STG_ROWH + chl] = __floats2half2_rn(d[0], d[1]);
                *(__half2*)&stage2[(i0 + 8) * STG_ROWH + chl] = __floats2half2_rn(d[2], d[3]);
            }
        }
        __syncthreads();
        int r = r0 + h;
#pragma unroll
        for (int it = 0; it < 8; it++) {
            int idx = tid + it * 256;             // 0..2047
            int row = idx >> 4, ck = idx & 15;
            int q = row & 63;
            int kk = (row < 64) ? r : 64 + r;
            uint4 v = *(uint4*)&stage2[row * STG_ROWH + ck * 8];
            *(uint4*)(g_Uh + ((size_t)(b * 64 + q) * 128 + kk) * CDIM + bn + ck * 8) = v;
        }
    }
}

// ---------------------------------------------------------------------------
// 4) Pass 2 (fp16 mma): per (b, q): out[64p x ch] = T2 * U + bias,
//    looping over all 6 channel tiles with double-buffered B.
//    A = T2h [64p][128k] 16KB (256B rows), B = U [128k][128ch] 32KB x2
// ---------------------------------------------------------------------------
#define P2_SMEM (16384 + 2 * 32768)

__global__ __launch_bounds__(256) void pass2_kernel(
    const float* __restrict__ bias, float* __restrict__ out)
{
    extern __shared__ char smem[];
    uint32_t sb = smem_u32(smem);
    uint32_t sbA = sb;
    int b = blockIdx.y, q = blockIdx.x;
    int tid = threadIdx.x;
    int wid = tid >> 5, lane = tid & 31;
    int wm = wid >> 2, wn = wid & 3;

    const __half* usrc = g_Uh + (size_t)(b * 64 + q) * 128 * CDIM;

    // prologue: A (T2) + B tile 0 -> group 0
#pragma unroll
    for (int c = 0; c < 4; c++) {
        int idx = tid + c * 256;
        int p = idx >> 4, ck = idx & 15;
        cp_async16(sbA + SWZ256(p * 256 + ck * 16), g_T2h + p * 128 + ck * 8);
    }
#pragma unroll
    for (int c = 0; c < 8; c++) {
        int idx = tid + c * 256;
        int k = idx >> 4, ck = idx & 15;
        cp_async16(sb + 16384 + SWZ256(k * 256 + ck * 16),
                   usrc + (size_t)k * CDIM + 0 + ck * 8);
    }
    CP_COMMIT();

    int l7 = lane & 7, sel = lane >> 3;
    int rsel = (sel & 1) * 8;
    int csel = (sel >> 1) * 16;
    int g1 = (lane >> 3) & 1;
    int g2 = (lane >> 4) * 16;

    for (int cht = 0; cht < 6; cht++) {
        __syncthreads();                     // prior compute done before overwriting other buf
        if (cht + 1 < 6) {
            uint32_t bbuf = sb + 16384 + ((cht + 1) & 1) * 32768;
            int c1 = (cht + 1) * 128;
#pragma unroll
            for (int c = 0; c < 8; c++) {
                int idx = tid + c * 256;
                int k = idx >> 4, ck = idx & 15;
                cp_async16(bbuf + SWZ256(k * 256 + ck * 16),
                           usrc + (size_t)k * CDIM + c1 + ck * 8);
            }
            CP_COMMIT();
            CP_WAIT1();
        } else {
            CP_WAIT0();
        }
        __syncthreads();

        uint32_t sbB = sb + 16384 + (cht & 1) * 32768;
        int c0 = cht * 128;

        float acc[2][4][4];
#pragma unroll
        for (int i = 0; i < 2; i++)
#pragma unroll
            for (int j = 0; j < 4; j++)
#pragma unroll
                for (int v = 0; v < 4; v++) acc[i][j][v] = 0.f;

#pragma unroll
        for (int ks = 0; ks < 8; ks++) {
            uint32_t afrag[2][4];
#pragma unroll
            for (int mt = 0; mt < 2; mt++) {
                int row = wm * 32 + mt * 16 + l7 + rsel;
                ldmx4(afrag[mt], sbA + SWZ256(row * 256 + ks * 32 + csel));
            }
#pragma unroll
            for (int ng = 0; ng < 2; ng++) {
                uint32_t bfrag[4];
                int row = ks * 16 + l7 + g1 * 8;
                int colb = wn * 64 + ng * 32 + g2;
                ldmx4t(bfrag, sbB + SWZ256(row * 256 + colb));
#pragma unroll
                for (int mt = 0; mt < 2; mt++) {
                    mma16816h(acc[mt][ng * 2 + 0], afrag[mt], bfrag[0], bfrag[1]);
                    mma16816h(acc[mt][ng * 2 + 1], afrag[mt], bfrag[2], bfrag[3]);
                }
            }
        }

        int rq = lane >> 2, cq = (lane & 3) * 2;
#pragma unroll
        for (int mt = 0; mt < 2; mt++) {
            int pbase = wm * 32 + mt * 16;
#pragma unroll
            for (int n8 = 0; n8 < 4; n8++) {
                float* d = acc[mt][n8];
                int ch = c0 + wn * 32 + n8 * 8 + cq;
                float2 bv = *(const float2*)(bias + ch);
                int p0 = pbase + rq, p1 = pbase + rq + 8;
                float* o0 = out + ((size_t)b * NTOK + p0 * 64 + q) * CDIM + ch;
                float* o1 = out + ((size_t)b * NTOK + p1 * 64 + q) * CDIM + ch;
                *(float2*)o0 = make_float2(d[0] + bv.x, d[1] + bv.y);
                *(float2*)o1 = make_float2(d[2] + bv.x, d[3] + bv.y);
            }
        }
    }
}

// ---------------------------------------------------------------------------
// launch
// ---------------------------------------------------------------------------
extern "C" void kernel_launch(void* const* d_in, const int* in_sizes, int n_in,
                              void* d_out, int out_size)
{
    const float* x      = (const float*)d_in[0];   // [8,4096,768]
    const float* qkv_w  = (const float*)d_in[1];   // [2304,768]
    const float* proj_w = (const float*)d_in[2];   // [768,768]
    const float* proj_b = (const float*)d_in[3];   // [768]
    float* out = (float*)d_out;

    cudaFuncSetAttribute(gemm_mma_kernel, cudaFuncAttributeMaxDynamicSharedMemorySize, GM_SMEM);
    cudaFuncSetAttribute(pass2_kernel,    cudaFuncAttributeMaxDynamicSharedMemorySize, P2_SMEM);

    init_tables_kernel<<<1, 256>>>();
    compute_M_kernel<<<dim3(CDIM / 64, CDIM / 64), 256>>>(qkv_w, proj_w);
    prep_b_kernel<<<dim3(CDIM / 32, CDIM / 32), 256>>>();
    prep_a_kernel<<<(int)(((size_t)BATCH * NTOK * CDIM / 8 + 255) / 256), 256>>>(x);
    gemm_mma_kernel<<<dim3(CDIM / 128, (BATCH * NTOK) / 128), 256, GM_SMEM>>>();
    pass2_kernel<<<dim3(64, BATCH), 256, P2_SMEM>>>(proj_b, out);
}

// round 12
// speedup vs baseline: 6.4135x; 1.0163x over previous
#include <cuda_runtime.h>
#include <cuda_bf16.h>
#include <cuda_fp16.h>
#include <cstdint>
#include <math.h>

// Problem constants
#define BATCH 8
#define NTOK  4096
#define CDIM  768

// ---------------------------------------------------------------------------
// device scratch (no runtime allocation allowed)
// ---------------------------------------------------------------------------
__device__ __align__(16) __half g_Ah[(size_t)BATCH * NTOK * CDIM];   // [32768][768] fp16 x
__device__ __align__(16) __half g_Bh[(size_t)CDIM * CDIM];           // [768 n][768 k] fp16 M^T
__device__ __align__(16) __half g_Uh[(size_t)BATCH * 64 * 128 * CDIM]; // [(b,q,k)][768] fp16 U
__device__ __align__(16) __half g_T1h[128 * 64];                     // [i][s] i<64: cos(i*s), else sin
__device__ __align__(16) __half g_T2h[64 * 128];                     // [p][k] k<64: cos(p*k), else -sin

// ---------------------------------------------------------------------------
// PTX helpers (baseline compute_103-safe)
// ---------------------------------------------------------------------------
__device__ __forceinline__ uint32_t smem_u32(const void* p) {
    uint32_t a;
    asm("{ .reg .u64 t; cvta.to.shared.u64 t, %1; cvt.u32.u64 %0, t; }" : "=r"(a) : "l"(p));
    return a;
}
__device__ __forceinline__ void cp_async16(uint32_t sa, const void* ga) {
    asm volatile("cp.async.cg.shared.global [%0], [%1], 16;" :: "r"(sa), "l"(ga));
}
#define CP_COMMIT() asm volatile("cp.async.commit_group;" ::: "memory")
#define CP_WAIT2()  asm volatile("cp.async.wait_group 2;" ::: "memory")
#define CP_WAIT1()  asm volatile("cp.async.wait_group 1;" ::: "memory")
#define CP_WAIT0()  asm volatile("cp.async.wait_group 0;" ::: "memory")
#define SWZ128(o)   ((o) ^ (((o) >> 3) & 0x70))
#define SWZ256(o)   ((o) ^ (((o) >> 4) & 0x70))

__device__ __forceinline__ void ldmx4(uint32_t* r, uint32_t addr) {
    asm volatile("ldmatrix.sync.aligned.m8n8.x4.shared.b16 {%0,%1,%2,%3}, [%4];"
                 : "=r"(r[0]), "=r"(r[1]), "=r"(r[2]), "=r"(r[3]) : "r"(addr));
}
__device__ __forceinline__ void ldmx4t(uint32_t* r, uint32_t addr) {
    asm volatile("ldmatrix.sync.aligned.m8n8.x4.trans.shared.b16 {%0,%1,%2,%3}, [%4];"
                 : "=r"(r[0]), "=r"(r[1]), "=r"(r[2]), "=r"(r[3]) : "r"(addr));
}
__device__ __forceinline__ void mma16816h(float* d, const uint32_t* a, uint32_t b0, uint32_t b1) {
    asm volatile("mma.sync.aligned.m16n8k16.row.col.f32.f16.f16.f32 "
                 "{%0,%1,%2,%3},{%4,%5,%6,%7},{%8,%9},{%0,%1,%2,%3};"
                 : "+f"(d[0]), "+f"(d[1]), "+f"(d[2]), "+f"(d[3])
                 : "r"(a[0]), "r"(a[1]), "r"(a[2]), "r"(a[3]), "r"(b0), "r"(b1));
}

#define STG1_ROWH 264   /* 528B row stride (odd multiple of 16B): conflict-free */

// ---------------------------------------------------------------------------
// 0) fp16 twiddle tables
// ---------------------------------------------------------------------------
__global__ void init_tables_kernel() {
    int tid = threadIdx.x;
    const double TWO_PI = 6.283185307179586476925286766559;
    for (int i = tid; i < 128 * 64; i += 256) {
        int row = i >> 6, s = i & 63;
        double ang = TWO_PI * (double)(((row & 63) * s) & 63) / 64.0;
        float v = (row < 64) ? (float)cos(ang) : (float)sin(ang);
        g_T1h[i] = __float2half_rn(v);
    }
    for (int i = tid; i < 64 * 128; i += 256) {
        int p = i >> 7, k = i & 127;
        double ang = TWO_PI * (double)((p * (k & 63)) & 63) / 64.0;
        float v = (k < 64) ? (float)cos(ang) : (float)(-sin(ang));
        g_T2h[i] = __float2half_rn(v);
    }
}

// ---------------------------------------------------------------------------
// 1) Direct B build: g_Bh[n][k] = fp16( sum_j proj_w[n][j] * qkv_w[2C+j][k] )
//    64x64 tile, 4x4 micro, 256 threads. Both operands coalesced; no g_M.
// ---------------------------------------------------------------------------
__global__ __launch_bounds__(256) void compute_B_kernel(
    const float* __restrict__ qkv_w, const float* __restrict__ proj_w)
{
    __shared__ float sA[16][68];   // [jj][nn]  A[n][j] = proj_w[n][j]
    __shared__ float sB[16][68];   // [jj][kk]  B[j][k] = qkv_w[2C+j][k]
    int n0 = blockIdx.y * 64, k0 = blockIdx.x * 64;
    int tid = threadIdx.x;
    int ty = (tid >> 4) << 2, tx = (tid & 15) << 2;
    float acc[4][4];
#pragma unroll
    for (int i = 0; i < 4; i++)
#pragma unroll
        for (int j = 0; j < 4; j++) acc[i][j] = 0.f;

    for (int j0 = 0; j0 < CDIM; j0 += 16) {
        // sA: float4 along j from proj_w rows, transposed into [jj][nn]
        {
            int nn = tid >> 2, jq = (tid & 3) * 4;
            float4 v = *(const float4*)(proj_w + (size_t)(n0 + nn) * CDIM + j0 + jq);
            sA[jq + 0][nn] = v.x; sA[jq + 1][nn] = v.y;
            sA[jq + 2][nn] = v.z; sA[jq + 3][nn] = v.w;
        }
        // sB: coalesced over k
#pragma unroll
        for (int c = 0; c < 4; c++) {
            int e = tid + c * 256;
            int jj = e >> 6, kk = e & 63;
            sB[jj][kk] = qkv_w[(size_t)(2 * CDIM + j0 + jj) * CDIM + k0 + kk];
        }
        __syncthreads();
#pragma unroll
        for (int jj = 0; jj < 16; jj++) {
            float a[4], b[4];
            *(float4*)a = *(const float4*)&sA[jj][ty];
            *(float4*)b = *(const float4*)&sB[jj][tx];
#pragma unroll
            for (int i = 0; i < 4; i++)
#pragma unroll
                for (int j = 0; j < 4; j++)
                    acc[i][j] += a[i] * b[j];
        }
        __syncthreads();
    }
#pragma unroll
    for (int i = 0; i < 4; i++) {
        __half2 h0 = __floats2half2_rn(acc[i][0], acc[i][1]);
        __half2 h1 = __floats2half2_rn(acc[i][2], acc[i][3]);
        __half2* dst = (__half2*)(g_Bh + (size_t)(n0 + ty + i) * CDIM + k0 + tx);
        dst[0] = h0; dst[1] = h1;
    }
}

// ---------------------------------------------------------------------------
// 2) x -> fp16 (8 floats -> 16B store per thread)
// ---------------------------------------------------------------------------
__global__ __launch_bounds__(256) void prep_a_kernel(const float* __restrict__ x) {
    size_t i8 = ((size_t)blockIdx.x * 256 + threadIdx.x) * 8;
    if (i8 >= (size_t)BATCH * NTOK * CDIM) return;
    float4 v0 = *(const float4*)(x + i8);
    float4 v1 = *(const float4*)(x + i8 + 4);
    __half2 h[4];
    h[0] = __floats2half2_rn(v0.x, v0.y);
    h[1] = __floats2half2_rn(v0.z, v0.w);
    h[2] = __floats2half2_rn(v1.x, v1.y);
    h[3] = __floats2half2_rn(v1.z, v1.w);
    *(uint4*)(g_Ah + i8) = *(uint4*)h;
}

// ---------------------------------------------------------------------------
// 3) Fused GEMM + pass1. CTA tile 128(M) x 256(N), K-tile 64, 4-stage ring.
//    8 warps as 2m x 4n, warp tile 64x64.
//    Epilogue: Z fp16 -> smem stage -> fused U = T1 * Z -> g_Uh.
// ---------------------------------------------------------------------------
#define GM_NT 12
#define STG_BYTES 49152          /* A 16KB + B 32KB per stage */
#define NSTAGE 4
#define GM_SMEM (NSTAGE * STG_BYTES + 16384)   /* + T1 (16KB) */

__device__ __forceinline__ void gemm_load_tile(uint32_t sb, int tid, int bm, int bn,
                                               int kt, int slot) {
    int koff = kt * 64;
    uint32_t abase = sb + slot * STG_BYTES;
    uint32_t bbase = abase + 16384;
#pragma unroll
    for (int c = 0; c < 4; c++) {
        int ch = tid + c * 256;               // 0..1023: 128 rows x 8 chunks
        int row = ch >> 3, kc = ch & 7;
        cp_async16(abase + SWZ128(row * 128 + kc * 16),
                   g_Ah + (size_t)(bm + row) * CDIM + koff + kc * 8);
    }
#pragma unroll
    for (int c = 0; c < 8; c++) {
        int ch = tid + c * 256;               // 0..2047: 256 rows x 8 chunks
        int row = ch >> 3, kc = ch & 7;
        cp_async16(bbase + SWZ128(row * 128 + kc * 16),
                   g_Bh + (size_t)(bn + row) * CDIM + koff + kc * 8);
    }
}

__global__ __launch_bounds__(256) void gemm_mma_kernel() {
    extern __shared__ char smem[];
    uint32_t sb = smem_u32(smem);
    uint32_t sbT1 = sb + NSTAGE * STG_BYTES;
    __half* stage1 = (__half*)smem;                             // Z tile 128x264 (67584B)
    __half* stage2 = (__half*)(smem + 128 * STG1_ROWH * 2);     // U tile 128x264 (67584B)
    uint32_t sbS1 = sb;
    int tid = threadIdx.x;
    int wid = tid >> 5, lane = tid & 31;
    int wm = wid >> 2, wn = wid & 3;          // 2m x 4n
    int bm = blockIdx.y * 128;
    int bn = blockIdx.x * 256;
    int b = bm >> 12;                 // batch
    int r0 = (bm >> 6) & 63;          // first spatial row of this tile

    int l7 = lane & 7, sel = lane >> 3;
    int rsel = (sel & 1) * 8;
    int csel = (sel >> 1) * 16;
    int g1 = (lane >> 3) & 1;
    int g2 = (lane >> 4) * 16;

    float acc[4][8][4];
#pragma unroll
    for (int i = 0; i < 4; i++)
#pragma unroll
        for (int j = 0; j < 8; j++)
#pragma unroll
            for (int v = 0; v < 4; v++) acc[i][j][v] = 0.f;

    // prologue: T1 + tile0 in group 0; tiles 1,2 in groups 1,2
#pragma unroll
    for (int c = 0; c < 4; c++) {
        int o = (tid + c * 256) * 16;
        cp_async16(sbT1 + SWZ128(o), (const char*)g_T1h + o);
    }
    gemm_load_tile(sb, tid, bm, bn, 0, 0);
    CP_COMMIT();
    gemm_load_tile(sb, tid, bm, bn, 1, 1);
    CP_COMMIT();
    gemm_load_tile(sb, tid, bm, bn, 2, 2);
    CP_COMMIT();

    for (int kt = 0; kt < GM_NT; kt++) {
        CP_WAIT2();
        __syncthreads();

        if (kt + NSTAGE - 1 < GM_NT)
            gemm_load_tile(sb, tid, bm, bn, kt + NSTAGE - 1, (kt + NSTAGE - 1) & (NSTAGE - 1));
        CP_COMMIT();

        uint32_t ab = sb + (kt & (NSTAGE - 1)) * STG_BYTES;
        uint32_t bb = ab + 16384;
#pragma unroll
        for (int ks = 0; ks < 4; ks++) {
            uint32_t afrag[4][4];
#pragma unroll
            for (int mt = 0; mt < 4; mt++) {
                int row = wm * 64 + mt * 16 + l7 + rsel;
                ldmx4(afrag[mt], ab + SWZ128(row * 128 + ks * 32 + csel));
            }
#pragma unroll
            for (int nt = 0; nt < 4; nt++) {
                uint32_t bfrag[4];
                int row = wn * 64 + nt * 16 + l7 + rsel;
                ldmx4(bfrag, bb + SWZ128(row * 128 + ks * 32 + csel));
#pragma unroll
                for (int mt = 0; mt < 4; mt++) {
                    mma16816h(acc[mt][nt * 2 + 0], afrag[mt], bfrag[0], bfrag[2]);
                    mma16816h(acc[mt][nt * 2 + 1], afrag[mt], bfrag[1], bfrag[3]);
                }
            }
        }
    }

    // ---- stage Z (fp16) into stage1 ----
    CP_WAIT0();
    __syncthreads();
    int rq = lane >> 2, cq = (lane & 3) * 2;
#pragma unroll
    for (int mt = 0; mt < 4; mt++) {
#pragma unroll
        for (int n8 = 0; n8 < 8; n8++) {
            float* d = acc[mt][n8];
            int row = wm * 64 + mt * 16 + rq;
            int c = wn * 64 + n8 * 8 + cq;
            *(__half2*)&stage1[row * STG1_ROWH + c] = __floats2half2_rn(d[0], d[1]);
            *(__half2*)&stage1[(row + 8) * STG1_ROWH + c] = __floats2half2_rn(d[2], d[3]);
        }
    }
    __syncthreads();

    // ---- fused pass1: per half h (spatial row r0+h): U[128i x 256ch] = T1 * Z_h ----
#pragma unroll
    for (int h = 0; h < 2; h++) {
        float uacc[4][8][4];
#pragma unroll
        for (int i = 0; i < 4; i++)
#pragma unroll
            for (int j = 0; j < 8; j++)
#pragma unroll
                for (int v = 0; v < 4; v++) uacc[i][j][v] = 0.f;

#pragma unroll
        for (int ks = 0; ks < 4; ks++) {
            uint32_t afrag[4][4];
#pragma unroll
            for (int mt = 0; mt < 4; mt++) {
                int row = wm * 64 + mt * 16 + l7 + rsel;
                ldmx4(afrag[mt], sbT1 + SWZ128(row * 128 + ks * 32 + csel));
            }
#pragma unroll
            for (int ng = 0; ng < 4; ng++) {
                uint32_t bfrag[4];
                int srow = h * 64 + ks * 16 + l7 + g1 * 8;
                int colb = wn * 128 + ng * 32 + g2;
                ldmx4t(bfrag, sbS1 + srow * (STG1_ROWH * 2) + colb);
#pragma unroll
                for (int mt = 0; mt < 4; mt++) {
                    mma16816h(uacc[mt][ng * 2 + 0], afrag[mt], bfrag[0], bfrag[1]);
                    mma16816h(uacc[mt][ng * 2 + 1], afrag[mt], bfrag[2], bfrag[3]);
                }
            }
        }

        if (h == 1) __syncthreads();      // prior stage2 store-read complete
#pragma unroll
        for (int mt = 0; mt < 4; mt++) {
#pragma unroll
            for (int n8 = 0; n8 < 8; n8++) {
                float* d = uacc[mt][n8];
                int i0 = wm * 64 + mt * 16 + rq;
                int chl = wn * 64 + n8 * 8 + cq;
                *(__half2*)&stage2[i0 * STG1_ROWH + chl] = __floats2half2_rn(d[0], d[1]);
                *(__half2*)&stage2[(i0 + 8) * STG1_ROWH + chl] = __floats2half2_rn(d[2], d[3]);
            }
        }
        __syncthreads();
        int r = r0 + h;
#pragma unroll
        for (int it = 0; it < 16; it++) {
            int idx = tid + it * 256;             // 0..4095: 128 rows x 32 chunks
            int row = idx >> 5, ck = idx & 31;
            int q = row & 63;
            int kk = (row < 64) ? r : 64 + r;
            uint4 v = *(uint4*)&stage2[row * STG1_ROWH + ck * 8];
            *(uint4*)(g_Uh + ((size_t)(b * 64 + q) * 128 + kk) * CDIM + bn + ck * 8) = v;
        }
    }
}

// ---------------------------------------------------------------------------
// 4) Pass 2 (fp16 mma): per (b, q): out[64p x ch] = T2 * U + bias,
//    looping over all 6 channel tiles with double-buffered B.
// ---------------------------------------------------------------------------
#define P2_SMEM (16384 + 2 * 32768)

__global__ __launch_bounds__(256) void pass2_kernel(
    const float* __restrict__ bias, float* __restrict__ out)
{
    extern __shared__ char smem[];
    uint32_t sb = smem_u32(smem);
    uint32_t sbA = sb;
    int b = blockIdx.y, q = blockIdx.x;
    int tid = threadIdx.x;
    int wid = tid >> 5, lane = tid & 31;
    int wm = wid >> 2, wn = wid & 3;

    const __half* usrc = g_Uh + (size_t)(b * 64 + q) * 128 * CDIM;

    // prologue: A (T2) + B tile 0 -> group 0
#pragma unroll
    for (int c = 0; c < 4; c++) {
        int idx = tid + c * 256;
        int p = idx >> 4, ck = idx & 15;
        cp_async16(sbA + SWZ256(p * 256 + ck * 16), g_T2h + p * 128 + ck * 8);
    }
#pragma unroll
    for (int c = 0; c < 8; c++) {
        int idx = tid + c * 256;
        int k = idx >> 4, ck = idx & 15;
        cp_async16(sb + 16384 + SWZ256(k * 256 + ck * 16),
                   usrc + (size_t)k * CDIM + 0 + ck * 8);
    }
    CP_COMMIT();

    int l7 = lane & 7, sel = lane >> 3;
    int rsel = (sel & 1) * 8;
    int csel = (sel >> 1) * 16;
    int g1 = (lane >> 3) & 1;
    int g2 = (lane >> 4) * 16;

    for (int cht = 0; cht < 6; cht++) {
        __syncthreads();
        if (cht + 1 < 6) {
            uint32_t bbuf = sb + 16384 + ((cht + 1) & 1) * 32768;
            int c1 = (cht + 1) * 128;
#pragma unroll
            for (int c = 0; c < 8; c++) {
                int idx = tid + c * 256;
                int k = idx >> 4, ck = idx & 15;
                cp_async16(bbuf + SWZ256(k * 256 + ck * 16),
                           usrc + (size_t)k * CDIM + c1 + ck * 8);
            }
            CP_COMMIT();
            CP_WAIT1();
        } else {
            CP_WAIT0();
        }
        __syncthreads();

        uint32_t sbB = sb + 16384 + (cht & 1) * 32768;
        int c0 = cht * 128;

        float acc[2][4][4];
#pragma unroll
        for (int i = 0; i < 2; i++)
#pragma unroll
            for (int j = 0; j < 4; j++)
#pragma unroll
                for (int v = 0; v < 4; v++) acc[i][j][v] = 0.f;

#pragma unroll
        for (int ks = 0; ks < 8; ks++) {
            uint32_t afrag[2][4];
#pragma unroll
            for (int mt = 0; mt < 2; mt++) {
                int row = wm * 32 + mt * 16 + l7 + rsel;
                ldmx4(afrag[mt], sbA + SWZ256(row * 256 + ks * 32 + csel));
            }
#pragma unroll
            for (int ng = 0; ng < 2; ng++) {
                uint32_t bfrag[4];
                int row = ks * 16 + l7 + g1 * 8;
                int colb = wn * 64 + ng * 32 + g2;
                ldmx4t(bfrag, sbB + SWZ256(row * 256 + colb));
#pragma unroll
                for (int mt = 0; mt < 2; mt++) {
                    mma16816h(acc[mt][ng * 2 + 0], afrag[mt], bfrag[0], bfrag[1]);
                    mma16816h(acc[mt][ng * 2 + 1], afrag[mt], bfrag[2], bfrag[3]);
                }
            }
        }

        int rq = lane >> 2, cq = (lane & 3) * 2;
#pragma unroll
        for (int mt = 0; mt < 2; mt++) {
            int pbase = wm * 32 + mt * 16;
#pragma unroll
            for (int n8 = 0; n8 < 4; n8++) {
                float* d = acc[mt][n8];
                int ch = c0 + wn * 32 + n8 * 8 + cq;
                float2 bv = *(const float2*)(bias + ch);
                int p0 = pbase + rq, p1 = pbase + rq + 8;
                float* o0 = out + ((size_t)b * NTOK + p0 * 64 + q) * CDIM + ch;
                float* o1 = out + ((size_t)b * NTOK + p1 * 64 + q) * CDIM + ch;
                *(float2*)o0 = make_float2(d[0] + bv.x, d[1] + bv.y);
                *(float2*)o1 = make_float2(d[2] + bv.x, d[3] + bv.y);
            }
        }
    }
}

// ---------------------------------------------------------------------------
// launch
// ---------------------------------------------------------------------------
extern "C" void kernel_launch(void* const* d_in, const int* in_sizes, int n_in,
                              void* d_out, int out_size)
{
    const float* x      = (const float*)d_in[0];   // [8,4096,768]
    const float* qkv_w  = (const float*)d_in[1];   // [2304,768]
    const float* proj_w = (const float*)d_in[2];   // [768,768]
    const float* proj_b = (const float*)d_in[3];   // [768]
    float* out = (float*)d_out;

    cudaFuncSetAttribute(gemm_mma_kernel, cudaFuncAttributeMaxDynamicSharedMemorySize, GM_SMEM);
    cudaFuncSetAttribute(pass2_kernel,    cudaFuncAttributeMaxDynamicSharedMemorySize, P2_SMEM);

    init_tables_kernel<<<1, 256>>>();
    compute_B_kernel<<<dim3(CDIM / 64, CDIM / 64), 256>>>(qkv_w, proj_w);
    prep_a_kernel<<<(int)(((size_t)BATCH * NTOK * CDIM / 8 + 255) / 256), 256>>>(x);
    gemm_mma_kernel<<<dim3(CDIM / 256, (BATCH * NTOK) / 128), 256, GM_SMEM>>>();
    pass2_kernel<<<dim3(64, BATCH), 256, P2_SMEM>>>(proj_b, out);
}